// round 1
// baseline (speedup 1.0000x reference)
#include <cuda_runtime.h>
#include <math.h>

#define NN    100000
#define F_IN  128
#define H1DIM 192     // 64 st + 64 ts + 64 all
#define H2DIM 128
#define NCLS  16

// ---------------- device scratch (static, no allocation) ----------------
__device__ float g_hlin [(size_t)NN * H1DIM];  // x @ [W_st|W_ts|W1]
__device__ float g_agg1 [(size_t)NN * H1DIM];  // agg1 -> h1 (in place)
__device__ float g_h2lin[(size_t)NN * H2DIM];  // h1 @ W2
__device__ float g_agg2 [(size_t)NN * H2DIM];  // agg2 -> h2 (in place)
__device__ float g_h3lin[(size_t)NN * NCLS];   // h2 @ W3
__device__ float g_cnt  [3 * NN];              // [st|ts|all] edge counts -> dinv (in place)

// ---------------- zero all accumulators + counters + d_out ----------------
__global__ void zero_prep(float* __restrict__ out) {
    const long n1 = (long)NN * H1DIM / 4;
    const long n2 = (long)NN * H2DIM / 4;
    const long n3 = (long)NN * NCLS  / 4;
    const long n4 = 3L * NN / 4;
    long i = (long)blockIdx.x * blockDim.x + threadIdx.x;
    float4 z = make_float4(0.f, 0.f, 0.f, 0.f);
    if      (i < n1)                ((float4*)g_agg1)[i] = z;
    else if (i < n1 + n2)           ((float4*)g_agg2)[i - n1] = z;
    else if (i < n1 + n2 + n3)      ((float4*)out)[i - n1 - n2] = z;
    else if (i < n1 + n2 + n3 + n4) ((float4*)g_cnt)[i - n1 - n2 - n3] = z;
}

// ---------------- per-branch degree counting ----------------
__global__ void deg_kernel(const int* __restrict__ src, const int* __restrict__ dst,
                           const int* __restrict__ rev, int E) {
    int e = blockIdx.x * blockDim.x + threadIdx.x;
    if (e >= E) return;
    int d = dst[e];
    atomicAdd(&g_cnt[2 * NN + d], 1.0f);
    atomicAdd(&g_cnt[(rev[e] ? NN : 0) + d], 1.0f);
}

// counts -> dinv = rsqrt(count + 1)  (in place)
__global__ void dinv_kernel() {
    int i = blockIdx.x * blockDim.x + threadIdx.x;
    if (i < 3 * NN) g_cnt[i] = rsqrtf(g_cnt[i] + 1.0f);
}

// ---------------- generic tiled SGEMM: C[M,Nc] = A[M,K] @ B[K,Nc] ----------------
// BM=128 BN=64 BK=16, 256 threads, 8x4 register tile per thread.
// ldb == Nc (weights contiguous). C pre-offset by caller; ldc passed in.
__global__ void sgemm_kernel(const float* __restrict__ A, const float* __restrict__ B,
                             float* __restrict__ C, int M, int Nc, int K, int ldc) {
    const int BM = 128, BN = 64, BK = 16;
    __shared__ float As[BK][BM];
    __shared__ float Bs[BK][BN];
    int tid = threadIdx.x;
    int rowBlock = blockIdx.x * BM;
    int colBlock = blockIdx.y * BN;

    int tr = tid >> 4;          // 0..15  -> rows tr*8..+7
    int tc = tid & 15;          // 0..15  -> cols tc*4..+3
    float acc[8][4];
    #pragma unroll
    for (int i = 0; i < 8; i++)
        #pragma unroll
        for (int j = 0; j < 4; j++) acc[i][j] = 0.f;

    int arow = tid >> 2;            // 0..63
    int acol = (tid & 3) << 2;      // 0,4,8,12
    int brow = tid >> 4;            // 0..15
    int bcol = (tid & 15) << 2;     // 0..60

    for (int k0 = 0; k0 < K; k0 += BK) {
        #pragma unroll
        for (int h = 0; h < 2; h++) {
            int r = arow + h * 64;
            int grow = rowBlock + r;
            float4 va = make_float4(0.f, 0.f, 0.f, 0.f);
            if (grow < M) va = *(const float4*)(A + (size_t)grow * K + k0 + acol);
            As[acol + 0][r] = va.x;
            As[acol + 1][r] = va.y;
            As[acol + 2][r] = va.z;
            As[acol + 3][r] = va.w;
        }
        {
            int gcol = colBlock + bcol;
            float4 vb = make_float4(0.f, 0.f, 0.f, 0.f);
            if (gcol + 3 < Nc) {
                vb = *(const float4*)(B + (size_t)(k0 + brow) * Nc + gcol);
            } else {
                float t0 = (gcol + 0 < Nc) ? B[(size_t)(k0 + brow) * Nc + gcol + 0] : 0.f;
                float t1 = (gcol + 1 < Nc) ? B[(size_t)(k0 + brow) * Nc + gcol + 1] : 0.f;
                float t2 = (gcol + 2 < Nc) ? B[(size_t)(k0 + brow) * Nc + gcol + 2] : 0.f;
                float t3 = (gcol + 3 < Nc) ? B[(size_t)(k0 + brow) * Nc + gcol + 3] : 0.f;
                vb = make_float4(t0, t1, t2, t3);
            }
            Bs[brow][bcol + 0] = vb.x;
            Bs[brow][bcol + 1] = vb.y;
            Bs[brow][bcol + 2] = vb.z;
            Bs[brow][bcol + 3] = vb.w;
        }
        __syncthreads();
        #pragma unroll
        for (int kk = 0; kk < BK; kk++) {
            float a[8], b[4];
            #pragma unroll
            for (int i = 0; i < 8; i++) a[i] = As[kk][tr * 8 + i];
            #pragma unroll
            for (int j = 0; j < 4; j++) b[j] = Bs[kk][tc * 4 + j];
            #pragma unroll
            for (int i = 0; i < 8; i++)
                #pragma unroll
                for (int j = 0; j < 4; j++) acc[i][j] += a[i] * b[j];
        }
        __syncthreads();
    }
    #pragma unroll
    for (int i = 0; i < 8; i++) {
        int grow = rowBlock + tr * 8 + i;
        if (grow >= M) continue;
        #pragma unroll
        for (int j = 0; j < 4; j++) {
            int gcol = colBlock + tc * 4 + j;
            if (gcol < Nc) C[(size_t)grow * ldc + gcol] = acc[i][j];
        }
    }
}

// ---------------- layer-1 scatter: masked branch (64) + all branch (64), warp/edge ----------------
__global__ void scatter1(const int* __restrict__ src, const int* __restrict__ dst,
                         const int* __restrict__ rev, int E) {
    long gt = (long)blockIdx.x * blockDim.x + threadIdx.x;
    int e = (int)(gt >> 5);
    if (e >= E) return;
    int lane = (int)(gt & 31);
    int s = src[e], d = dst[e];
    if (lane < 16) {
        int r = rev[e];
        const float* dv = g_cnt + (r ? NN : 0);
        float coef = dv[s] * dv[d];
        int cb = r ? 64 : 0;
        float4 v = *(const float4*)(g_hlin + (size_t)s * H1DIM + cb + lane * 4);
        v.x *= coef; v.y *= coef; v.z *= coef; v.w *= coef;
        atomicAdd((float4*)(g_agg1 + (size_t)d * H1DIM + cb + lane * 4), v);
    } else {
        const float* dv = g_cnt + 2 * NN;
        float coef = dv[s] * dv[d];
        int i = lane - 16;
        float4 v = *(const float4*)(g_hlin + (size_t)s * H1DIM + 128 + i * 4);
        v.x *= coef; v.y *= coef; v.z *= coef; v.w *= coef;
        atomicAdd((float4*)(g_agg1 + (size_t)d * H1DIM + 128 + i * 4), v);
    }
}

// ---------------- finalize layer 1: h1 = relu(agg + hlin*dinv^2 + bias), in place ----------------
__global__ void finalize1(const float* __restrict__ b_st, const float* __restrict__ b_ts,
                          const float* __restrict__ b1) {
    long idx = (long)blockIdx.x * blockDim.x + threadIdx.x;   // float4 index
    if (idx >= (long)NN * (H1DIM / 4)) return;
    int node = (int)(idx / (H1DIM / 4));
    int c4 = (int)(idx % (H1DIM / 4));
    int col = c4 * 4;
    float dv; const float* bias; int bcol;
    if (col < 64)       { dv = g_cnt[node];           bias = b_st; bcol = col; }
    else if (col < 128) { dv = g_cnt[NN + node];      bias = b_ts; bcol = col - 64; }
    else                { dv = g_cnt[2 * NN + node];  bias = b1;   bcol = col - 128; }
    float self = dv * dv;
    float4 a = ((const float4*)g_agg1)[idx];
    float4 h = ((const float4*)g_hlin)[idx];
    float4 bb = *(const float4*)(bias + bcol);
    float4 r;
    r.x = fmaxf(a.x + h.x * self + bb.x, 0.f);
    r.y = fmaxf(a.y + h.y * self + bb.y, 0.f);
    r.z = fmaxf(a.z + h.z * self + bb.z, 0.f);
    r.w = fmaxf(a.w + h.w * self + bb.w, 0.f);
    ((float4*)g_agg1)[idx] = r;
}

// ---------------- layer-2 scatter: 128 floats = 32 float4, warp/edge ----------------
__global__ void scatter2(const int* __restrict__ src, const int* __restrict__ dst, int E) {
    long gt = (long)blockIdx.x * blockDim.x + threadIdx.x;
    int e = (int)(gt >> 5);
    if (e >= E) return;
    int lane = (int)(gt & 31);
    int s = src[e], d = dst[e];
    const float* dv = g_cnt + 2 * NN;
    float coef = dv[s] * dv[d];
    float4 v = ((const float4*)(g_h2lin + (size_t)s * H2DIM))[lane];
    v.x *= coef; v.y *= coef; v.z *= coef; v.w *= coef;
    atomicAdd(((float4*)(g_agg2 + (size_t)d * H2DIM)) + lane, v);
}

// ---------------- finalize layer 2: h2 = agg + h2lin*dinv^2 + b2 (no relu), in place ----------------
__global__ void finalize2(const float* __restrict__ b2) {
    long idx = (long)blockIdx.x * blockDim.x + threadIdx.x;
    if (idx >= (long)NN * (H2DIM / 4)) return;
    int node = (int)(idx / (H2DIM / 4));
    int col = (int)(idx % (H2DIM / 4)) * 4;
    float dv = g_cnt[2 * NN + node];
    float self = dv * dv;
    float4 a = ((const float4*)g_agg2)[idx];
    float4 h = ((const float4*)g_h2lin)[idx];
    float4 bb = *(const float4*)(b2 + col);
    float4 r;
    r.x = a.x + h.x * self + bb.x;
    r.y = a.y + h.y * self + bb.y;
    r.z = a.z + h.z * self + bb.z;
    r.w = a.w + h.w * self + bb.w;
    ((float4*)g_agg2)[idx] = r;
}

// ---------------- layer-3 scatter: 16 floats = 4 float4, 4 lanes/edge ----------------
__global__ void scatter3(const int* __restrict__ src, const int* __restrict__ dst,
                         float* __restrict__ out, int E) {
    long gt = (long)blockIdx.x * blockDim.x + threadIdx.x;
    int e = (int)(gt >> 2);
    if (e >= E) return;
    int q = (int)(gt & 3);
    int s = src[e], d = dst[e];
    const float* dv = g_cnt + 2 * NN;
    float coef = dv[s] * dv[d];
    float4 v = ((const float4*)(g_h3lin + (size_t)s * NCLS))[q];
    v.x *= coef; v.y *= coef; v.z *= coef; v.w *= coef;
    atomicAdd(((float4*)(out + (size_t)d * NCLS)) + q, v);
}

// ---------------- finalize layer 3 + log_softmax, in place on d_out ----------------
__global__ void finalize3(float* __restrict__ out, const float* __restrict__ b3) {
    int i = blockIdx.x * blockDim.x + threadIdx.x;
    if (i >= NN) return;
    float dv = g_cnt[2 * NN + i];
    float self = dv * dv;
    float v[NCLS];
    float m = -1e30f;
    #pragma unroll
    for (int c = 0; c < NCLS; c++) {
        v[c] = out[(size_t)i * NCLS + c] + g_h3lin[(size_t)i * NCLS + c] * self + b3[c];
        m = fmaxf(m, v[c]);
    }
    float sum = 0.f;
    #pragma unroll
    for (int c = 0; c < NCLS; c++) sum += expf(v[c] - m);
    float l = logf(sum);
    #pragma unroll
    for (int c = 0; c < NCLS; c++) out[(size_t)i * NCLS + c] = v[c] - m - l;
}

// ---------------- host launcher ----------------
extern "C" void kernel_launch(void* const* d_in, const int* in_sizes, int n_in,
                              void* d_out, int out_size) {
    const float* x    = (const float*)d_in[0];
    const int*   eidx = (const int*)d_in[1];
    const int    E    = in_sizes[1] / 2;
    const int*   src  = eidx;
    const int*   dst  = eidx + E;
    const int*   rev  = (const int*)d_in[2];
    const float* W_st = (const float*)d_in[3];
    const float* b_st = (const float*)d_in[4];
    const float* W_ts = (const float*)d_in[5];
    const float* b_ts = (const float*)d_in[6];
    const float* W1   = (const float*)d_in[7];
    const float* b1   = (const float*)d_in[8];
    const float* W2   = (const float*)d_in[9];
    const float* b2   = (const float*)d_in[10];
    const float* W3   = (const float*)d_in[11];
    const float* b3   = (const float*)d_in[12];
    float* out = (float*)d_out;

    float *hlin, *agg1, *h2lin, *agg2, *h3lin;
    cudaGetSymbolAddress((void**)&hlin,  g_hlin);
    cudaGetSymbolAddress((void**)&agg1,  g_agg1);
    cudaGetSymbolAddress((void**)&h2lin, g_h2lin);
    cudaGetSymbolAddress((void**)&agg2,  g_agg2);
    cudaGetSymbolAddress((void**)&h3lin, g_h3lin);

    // 1. zero accumulators / counters / output
    {
        long total4 = ((long)NN * H1DIM + (long)NN * H2DIM + (long)NN * NCLS + 3L * NN) / 4;
        int blocks = (int)((total4 + 255) / 256);
        zero_prep<<<blocks, 256>>>(out);
    }
    // 2. degrees -> dinv
    deg_kernel<<<(E + 255) / 256, 256>>>(src, dst, rev, E);
    dinv_kernel<<<(3 * NN + 255) / 256, 256>>>();

    // 3. layer-1 linear: hlin = x @ [W_st | W_ts | W1]
    dim3 g1((NN + 127) / 128, 1);
    sgemm_kernel<<<g1, 256>>>(x, W_st, hlin + 0,   NN, 64, F_IN, H1DIM);
    sgemm_kernel<<<g1, 256>>>(x, W_ts, hlin + 64,  NN, 64, F_IN, H1DIM);
    sgemm_kernel<<<g1, 256>>>(x, W1,   hlin + 128, NN, 64, F_IN, H1DIM);

    // 4. layer-1 aggregation + finalize (relu)
    {
        long th = (long)E * 32;
        scatter1<<<(int)((th + 255) / 256), 256>>>(src, dst, rev, E);
        long f = (long)NN * (H1DIM / 4);
        finalize1<<<(int)((f + 255) / 256), 256>>>(b_st, b_ts, b1);
    }

    // 5. layer-2 linear: h2lin = h1 @ W2
    dim3 g2((NN + 127) / 128, (H2DIM + 63) / 64);
    sgemm_kernel<<<g2, 256>>>(agg1, W2, h2lin, NN, H2DIM, H1DIM, H2DIM);

    // 6. layer-2 aggregation + finalize (no relu)
    {
        long th = (long)E * 32;
        scatter2<<<(int)((th + 255) / 256), 256>>>(src, dst, E);
        long f = (long)NN * (H2DIM / 4);
        finalize2<<<(int)((f + 255) / 256), 256>>>(b2);
    }

    // 7. layer-3 linear: h3lin = h2 @ W3
    dim3 g3((NN + 127) / 128, 1);
    sgemm_kernel<<<g3, 256>>>(agg2, W3, h3lin, NN, NCLS, H2DIM, NCLS);

    // 8. layer-3 aggregation into d_out + log_softmax finalize
    {
        long th = (long)E * 4;
        scatter3<<<(int)((th + 255) / 256), 256>>>(src, dst, out, E);
        finalize3<<<(NN + 255) / 256, 256>>>(out, b3);
    }
}

// round 2
// speedup vs baseline: 1.3967x; 1.3967x over previous
#include <cuda_runtime.h>
#include <math.h>

#define NN    100000
#define F_IN  128
#define H1DIM 192     // 64 st + 64 ts + 64 all
#define H2DIM 128
#define NCLS  16
#define EMAX  1600000

// ---------------- device scratch (static, no allocation) ----------------
__device__ float g_hlin [(size_t)NN * H1DIM];  // x @ [W_st|W_ts|W1]
__device__ float g_h1   [(size_t)NN * H1DIM];  // relu(gcn layer1)
__device__ float g_h2lin[(size_t)NN * H2DIM];  // h1 @ W2
__device__ float g_h2   [(size_t)NN * H2DIM];  // gcn layer2
__device__ float g_h3lin[(size_t)NN * NCLS];   // h2 @ W3
__device__ float g_dinv [3 * NN];              // [st|ts|all] rsqrt(deg+1)
__device__ int   g_deg  [3 * NN];              // [st|ts|all] integer in-degree
__device__ int   g_off  [NN];                  // CSR offsets (exclusive scan of all-deg)
__device__ int   g_cur  [NN];                  // fill cursors
__device__ int   g_bsum [512];                 // scan partials
__device__ int   g_csrc [EMAX];                // packed src | (rev<<20), CSR order by dst
__device__ float g_coefA[EMAX];                // all-branch coef, CSR order
__device__ float g_coefM[EMAX];                // masked-branch coef, CSR order
__device__ float g_Wcat [F_IN * H1DIM];        // [W_st | W_ts | W1]

// ---------------- zero degree counters ----------------
__global__ void zero_deg() {
    int i = blockIdx.x * blockDim.x + threadIdx.x;
    if (i < 3 * NN) g_deg[i] = 0;
}

// ---------------- per-branch degree counting ----------------
__global__ void deg_kernel(const int* __restrict__ dst, const int* __restrict__ rev, int E) {
    int e = blockIdx.x * blockDim.x + threadIdx.x;
    if (e >= E) return;
    int d = dst[e];
    atomicAdd(&g_deg[2 * NN + d], 1);
    atomicAdd(&g_deg[(rev[e] ? NN : 0) + d], 1);
}

// counts -> dinv = rsqrt(count + 1)
__global__ void dinv_kernel() {
    int i = blockIdx.x * blockDim.x + threadIdx.x;
    if (i < 3 * NN) g_dinv[i] = rsqrtf((float)g_deg[i] + 1.0f);
}

// ---------------- scan (exclusive) of all-branch degrees -> g_off ----------------
__global__ void scan_block() {
    __shared__ int sh[256];
    int tid = threadIdx.x;
    int i = blockIdx.x * 256 + tid;
    int v = (i < NN) ? g_deg[2 * NN + i] : 0;
    sh[tid] = v;
    __syncthreads();
    #pragma unroll
    for (int off = 1; off < 256; off <<= 1) {
        int t = (tid >= off) ? sh[tid - off] : 0;
        __syncthreads();
        sh[tid] += t;
        __syncthreads();
    }
    if (i < NN) g_off[i] = sh[tid] - v;            // exclusive within block
    if (tid == 255) g_bsum[blockIdx.x] = sh[255];  // block total
}

__global__ void scan_partials(int nb) {
    __shared__ int sh[512];
    int tid = threadIdx.x;
    int v = (tid < nb) ? g_bsum[tid] : 0;
    sh[tid] = v;
    __syncthreads();
    #pragma unroll
    for (int off = 1; off < 512; off <<= 1) {
        int t = (tid >= off) ? sh[tid - off] : 0;
        __syncthreads();
        sh[tid] += t;
        __syncthreads();
    }
    if (tid < nb) g_bsum[tid] = sh[tid] - v;       // exclusive
}

__global__ void scan_add() {
    int i = blockIdx.x * blockDim.x + threadIdx.x;
    if (i >= NN) return;
    int o = g_off[i] + g_bsum[i >> 8];
    g_off[i] = o;
    g_cur[i] = o;
}

// ---------------- fill CSR: packed src|rev + per-edge coefficients ----------------
__global__ void fill_csr(const int* __restrict__ src, const int* __restrict__ dst,
                         const int* __restrict__ rev, int E) {
    int e = blockIdx.x * blockDim.x + threadIdx.x;
    if (e >= E) return;
    int s = src[e], d = dst[e], r = rev[e];
    int pos = atomicAdd(&g_cur[d], 1);
    g_csrc[pos] = s | (r << 20);
    g_coefA[pos] = g_dinv[2 * NN + s] * g_dinv[2 * NN + d];
    const float* dv = g_dinv + (r ? NN : 0);
    g_coefM[pos] = dv[s] * dv[d];
}

// ---------------- concat weights into [128,192] ----------------
__global__ void concat_w(const float* __restrict__ Wst, const float* __restrict__ Wts,
                         const float* __restrict__ W1f) {
    int i = blockIdx.x * blockDim.x + threadIdx.x;
    if (i >= F_IN * 64) return;
    int r = i >> 6, c = i & 63;
    g_Wcat[r * H1DIM + c]       = Wst[i];
    g_Wcat[r * H1DIM + 64 + c]  = Wts[i];
    g_Wcat[r * H1DIM + 128 + c] = W1f[i];
}

// ---------------- generic tiled SGEMM: C[M,Nc] = A[M,K] @ B[K,Nc] ----------------
// BM=128 BN=64 BK=16, 256 threads, 8x4 register tile per thread.
// blockIdx.x = column block (fastest -> same-row col-blocks adjacent for L2 reuse of A)
// blockIdx.y = row block
__global__ void __launch_bounds__(256)
sgemm_kernel(const float* __restrict__ A, const float* __restrict__ B,
             float* __restrict__ C, int M, int Nc, int K, int ldc) {
    const int BM = 128, BN = 64, BK = 16;
    __shared__ float As[BK][BM];
    __shared__ float Bs[BK][BN];
    int tid = threadIdx.x;
    int rowBlock = blockIdx.y * BM;
    int colBlock = blockIdx.x * BN;

    int tr = tid >> 4;
    int tc = tid & 15;
    float acc[8][4];
    #pragma unroll
    for (int i = 0; i < 8; i++)
        #pragma unroll
        for (int j = 0; j < 4; j++) acc[i][j] = 0.f;

    int arow = tid >> 2;
    int acol = (tid & 3) << 2;
    int brow = tid >> 4;
    int bcol = (tid & 15) << 2;

    for (int k0 = 0; k0 < K; k0 += BK) {
        #pragma unroll
        for (int h = 0; h < 2; h++) {
            int r = arow + h * 64;
            int grow = rowBlock + r;
            float4 va = make_float4(0.f, 0.f, 0.f, 0.f);
            if (grow < M) va = *(const float4*)(A + (size_t)grow * K + k0 + acol);
            As[acol + 0][r] = va.x;
            As[acol + 1][r] = va.y;
            As[acol + 2][r] = va.z;
            As[acol + 3][r] = va.w;
        }
        {
            int gcol = colBlock + bcol;
            float4 vb;
            if (gcol + 3 < Nc) {
                vb = *(const float4*)(B + (size_t)(k0 + brow) * Nc + gcol);
            } else {
                float t0 = (gcol + 0 < Nc) ? B[(size_t)(k0 + brow) * Nc + gcol + 0] : 0.f;
                float t1 = (gcol + 1 < Nc) ? B[(size_t)(k0 + brow) * Nc + gcol + 1] : 0.f;
                float t2 = (gcol + 2 < Nc) ? B[(size_t)(k0 + brow) * Nc + gcol + 2] : 0.f;
                float t3 = (gcol + 3 < Nc) ? B[(size_t)(k0 + brow) * Nc + gcol + 3] : 0.f;
                vb = make_float4(t0, t1, t2, t3);
            }
            Bs[brow][bcol + 0] = vb.x;
            Bs[brow][bcol + 1] = vb.y;
            Bs[brow][bcol + 2] = vb.z;
            Bs[brow][bcol + 3] = vb.w;
        }
        __syncthreads();
        #pragma unroll
        for (int kk = 0; kk < BK; kk++) {
            float a[8], b[4];
            #pragma unroll
            for (int i = 0; i < 8; i++) a[i] = As[kk][tr * 8 + i];
            #pragma unroll
            for (int j = 0; j < 4; j++) b[j] = Bs[kk][tc * 4 + j];
            #pragma unroll
            for (int i = 0; i < 8; i++)
                #pragma unroll
                for (int j = 0; j < 4; j++) acc[i][j] += a[i] * b[j];
        }
        __syncthreads();
    }
    #pragma unroll
    for (int i = 0; i < 8; i++) {
        int grow = rowBlock + tr * 8 + i;
        if (grow >= M) continue;
        #pragma unroll
        for (int j = 0; j < 4; j++) {
            int gcol = colBlock + tc * 4 + j;
            if (gcol < Nc) C[(size_t)grow * ldc + gcol] = acc[i][j];
        }
    }
}

// ---------------- layer-1 CSR gather: warp per node ----------------
// lanes 0-15: masked halves (st cols [0,64), ts cols [64,128)); lanes 16-31: all cols [128,192)
__global__ void gather1(const float* __restrict__ b_st, const float* __restrict__ b_ts,
                        const float* __restrict__ b1) {
    int node = blockIdx.x * (blockDim.x >> 5) + (threadIdx.x >> 5);
    if (node >= NN) return;
    int lane = threadIdx.x & 31;
    int beg = g_off[node];
    int end = beg + g_deg[2 * NN + node];

    float4 accS = make_float4(0.f, 0.f, 0.f, 0.f);
    float4 accT = make_float4(0.f, 0.f, 0.f, 0.f);
    float4 accA = make_float4(0.f, 0.f, 0.f, 0.f);

    for (int base = beg; base < end; base += 32) {
        int n = min(32, end - base);
        int msrc = 0; float mca = 0.f, mcm = 0.f;
        if (lane < n) {
            msrc = g_csrc[base + lane];
            mca  = g_coefA[base + lane];
            mcm  = g_coefM[base + lane];
        }
        for (int j = 0; j < n; j++) {
            int sp   = __shfl_sync(0xFFFFFFFFu, msrc, j);
            float ca = __shfl_sync(0xFFFFFFFFu, mca, j);
            float cm = __shfl_sync(0xFFFFFFFFu, mcm, j);
            int s = sp & 0xFFFFF;
            int r = sp >> 20;
            if (lane < 16) {
                float4 v = *(const float4*)(g_hlin + (size_t)s * H1DIM + (r ? 64 : 0) + lane * 4);
                if (r) {
                    accT.x += v.x * cm; accT.y += v.y * cm; accT.z += v.z * cm; accT.w += v.w * cm;
                } else {
                    accS.x += v.x * cm; accS.y += v.y * cm; accS.z += v.z * cm; accS.w += v.w * cm;
                }
            } else {
                float4 v = *(const float4*)(g_hlin + (size_t)s * H1DIM + 128 + (lane - 16) * 4);
                accA.x += v.x * ca; accA.y += v.y * ca; accA.z += v.z * ca; accA.w += v.w * ca;
            }
        }
    }

    float dvS = g_dinv[node], dvT = g_dinv[NN + node], dvA = g_dinv[2 * NN + node];
    const float* hrow = g_hlin + (size_t)node * H1DIM;
    float* orow = g_h1 + (size_t)node * H1DIM;
    if (lane < 16) {
        int c = lane * 4;
        float sS = dvS * dvS;
        float4 h = *(const float4*)(hrow + c);
        float4 bb = *(const float4*)(b_st + c);
        float4 o;
        o.x = fmaxf(accS.x + h.x * sS + bb.x, 0.f);
        o.y = fmaxf(accS.y + h.y * sS + bb.y, 0.f);
        o.z = fmaxf(accS.z + h.z * sS + bb.z, 0.f);
        o.w = fmaxf(accS.w + h.w * sS + bb.w, 0.f);
        *(float4*)(orow + c) = o;

        float sT = dvT * dvT;
        h = *(const float4*)(hrow + 64 + c);
        bb = *(const float4*)(b_ts + c);
        o.x = fmaxf(accT.x + h.x * sT + bb.x, 0.f);
        o.y = fmaxf(accT.y + h.y * sT + bb.y, 0.f);
        o.z = fmaxf(accT.z + h.z * sT + bb.z, 0.f);
        o.w = fmaxf(accT.w + h.w * sT + bb.w, 0.f);
        *(float4*)(orow + 64 + c) = o;
    } else {
        int c = (lane - 16) * 4;
        float sA = dvA * dvA;
        float4 h = *(const float4*)(hrow + 128 + c);
        float4 bb = *(const float4*)(b1 + c);
        float4 o;
        o.x = fmaxf(accA.x + h.x * sA + bb.x, 0.f);
        o.y = fmaxf(accA.y + h.y * sA + bb.y, 0.f);
        o.z = fmaxf(accA.z + h.z * sA + bb.z, 0.f);
        o.w = fmaxf(accA.w + h.w * sA + bb.w, 0.f);
        *(float4*)(orow + 128 + c) = o;
    }
}

// ---------------- layer-2 CSR gather: warp per node, 1 float4 per lane ----------------
__global__ void gather2(const float* __restrict__ b2) {
    int node = blockIdx.x * (blockDim.x >> 5) + (threadIdx.x >> 5);
    if (node >= NN) return;
    int lane = threadIdx.x & 31;
    int beg = g_off[node];
    int end = beg + g_deg[2 * NN + node];

    float4 acc = make_float4(0.f, 0.f, 0.f, 0.f);
    for (int base = beg; base < end; base += 32) {
        int n = min(32, end - base);
        int msrc = 0; float mca = 0.f;
        if (lane < n) {
            msrc = g_csrc[base + lane];
            mca  = g_coefA[base + lane];
        }
        for (int j = 0; j < n; j++) {
            int sp   = __shfl_sync(0xFFFFFFFFu, msrc, j);
            float ca = __shfl_sync(0xFFFFFFFFu, mca, j);
            int s = sp & 0xFFFFF;
            float4 v = ((const float4*)(g_h2lin + (size_t)s * H2DIM))[lane];
            acc.x += v.x * ca; acc.y += v.y * ca; acc.z += v.z * ca; acc.w += v.w * ca;
        }
    }
    float dv = g_dinv[2 * NN + node];
    float self = dv * dv;
    int c = lane * 4;
    float4 h = *(const float4*)(g_h2lin + (size_t)node * H2DIM + c);
    float4 bb = *(const float4*)(b2 + c);
    float4 o;
    o.x = acc.x + h.x * self + bb.x;
    o.y = acc.y + h.y * self + bb.y;
    o.z = acc.z + h.z * self + bb.z;
    o.w = acc.w + h.w * self + bb.w;
    *(float4*)(g_h2 + (size_t)node * H2DIM + c) = o;
}

// ---------------- layer-3 CSR gather + log_softmax: warp per node ----------------
// half-warps process alternating edges; lane&15 = class index
__global__ void gather3(float* __restrict__ out, const float* __restrict__ b3) {
    int node = blockIdx.x * (blockDim.x >> 5) + (threadIdx.x >> 5);
    if (node >= NN) return;
    int lane = threadIdx.x & 31;
    int half = lane >> 4;
    int l16 = lane & 15;
    int beg = g_off[node];
    int end = beg + g_deg[2 * NN + node];

    float acc = 0.f;
    for (int idx = beg + half; idx < end; idx += 2) {
        int sp = g_csrc[idx];
        float ca = g_coefA[idx];
        int s = sp & 0xFFFFF;
        acc += g_h3lin[(size_t)s * NCLS + l16] * ca;
    }
    acc += __shfl_down_sync(0xFFFFFFFFu, acc, 16);

    float dv = g_dinv[2 * NN + node];
    float self = dv * dv;
    float v = acc + g_h3lin[(size_t)node * NCLS + l16] * self + b3[l16];

    float m = v;
    #pragma unroll
    for (int o = 8; o > 0; o >>= 1) m = fmaxf(m, __shfl_xor_sync(0xFFFFFFFFu, m, o, 16));
    float s = expf(v - m);
    #pragma unroll
    for (int o = 8; o > 0; o >>= 1) s += __shfl_xor_sync(0xFFFFFFFFu, s, o, 16);
    float l = logf(s);
    if (lane < 16) out[(size_t)node * NCLS + l16] = v - m - l;
}

// ---------------- host launcher ----------------
extern "C" void kernel_launch(void* const* d_in, const int* in_sizes, int n_in,
                              void* d_out, int out_size) {
    const float* x    = (const float*)d_in[0];
    const int*   eidx = (const int*)d_in[1];
    const int    E    = in_sizes[1] / 2;
    const int*   src  = eidx;
    const int*   dst  = eidx + E;
    const int*   rev  = (const int*)d_in[2];
    const float* W_st = (const float*)d_in[3];
    const float* b_st = (const float*)d_in[4];
    const float* W_ts = (const float*)d_in[5];
    const float* b_ts = (const float*)d_in[6];
    const float* W1   = (const float*)d_in[7];
    const float* b1   = (const float*)d_in[8];
    const float* W2   = (const float*)d_in[9];
    const float* b2   = (const float*)d_in[10];
    const float* W3   = (const float*)d_in[11];
    const float* b3   = (const float*)d_in[12];
    float* out = (float*)d_out;

    float *hlin, *h1, *h2lin, *h2, *h3lin, *wcat;
    cudaGetSymbolAddress((void**)&hlin,  g_hlin);
    cudaGetSymbolAddress((void**)&h1,    g_h1);
    cudaGetSymbolAddress((void**)&h2lin, g_h2lin);
    cudaGetSymbolAddress((void**)&h2,    g_h2);
    cudaGetSymbolAddress((void**)&h3lin, g_h3lin);
    cudaGetSymbolAddress((void**)&wcat,  g_Wcat);

    const int nb = (NN + 255) / 256;   // scan blocks = 391

    // ---- CSR + normalization build ----
    zero_deg<<<(3 * NN + 255) / 256, 256>>>();
    deg_kernel<<<(E + 255) / 256, 256>>>(dst, rev, E);
    dinv_kernel<<<(3 * NN + 255) / 256, 256>>>();
    scan_block<<<nb, 256>>>();
    scan_partials<<<1, 512>>>(nb);
    scan_add<<<nb, 256>>>();
    fill_csr<<<(E + 255) / 256, 256>>>(src, dst, rev, E);
    concat_w<<<(F_IN * 64 + 255) / 256, 256>>>(W_st, W_ts, W1);

    // ---- layer 1: fused linear + gather ----
    dim3 g1(H1DIM / 64, (NN + 127) / 128);
    sgemm_kernel<<<g1, 256>>>(x, wcat, hlin, NN, H1DIM, F_IN, H1DIM);
    gather1<<<(NN * 32 + 255) / 256, 256>>>(b_st, b_ts, b1);

    // ---- layer 2 ----
    dim3 g2(H2DIM / 64, (NN + 127) / 128);
    sgemm_kernel<<<g2, 256>>>(h1, W2, h2lin, NN, H2DIM, H1DIM, H2DIM);
    gather2<<<(NN * 32 + 255) / 256, 256>>>(b2);

    // ---- layer 3 ----
    dim3 g3(1, (NN + 127) / 128);
    sgemm_kernel<<<g3, 256>>>(h2, W3, h3lin, NN, NCLS, H2DIM, NCLS);
    gather3<<<(NN * 32 + 255) / 256, 256>>>(out, b3);
}

// round 4
// speedup vs baseline: 1.6131x; 1.1550x over previous
#include <cuda_runtime.h>
#include <cuda_bf16.h>
#include <math.h>
#include <cstdint>

#define NN    100000
#define F_IN  128
#define H1DIM 192     // 64 st + 64 ts + 64 all
#define H2DIM 128
#define NCLS  16
#define EMAX  1600000

// ---------------- device scratch (static, no allocation) ----------------
__device__ float g_hlin [(size_t)NN * H1DIM];  // x @ [W_st|W_ts|W1] (fp32, gather1 input)
__device__ __nv_bfloat16 g_h1hi[(size_t)NN * H1DIM];  // h1 split hi
__device__ __nv_bfloat16 g_h1lo[(size_t)NN * H1DIM];  // h1 split lo
__device__ float g_h2lin[(size_t)NN * H2DIM];  // h1 @ W2 (fp32, gather2 input)
__device__ float g_h2   [(size_t)NN * H2DIM];  // gcn layer2 (fp32, sgemm3 input)
__device__ float g_h3lin[(size_t)NN * NCLS];   // h2 @ W3
__device__ __nv_bfloat16 g_xhi[(size_t)NN * F_IN];
__device__ __nv_bfloat16 g_xlo[(size_t)NN * F_IN];
__device__ __nv_bfloat16 g_B1hi[3 * 64 * F_IN];   // W1cat^T tiles [t][n][k]
__device__ __nv_bfloat16 g_B1lo[3 * 64 * F_IN];
__device__ __nv_bfloat16 g_B2hi[2 * 64 * H1DIM];  // W2^T tiles
__device__ __nv_bfloat16 g_B2lo[2 * 64 * H1DIM];
__device__ float g_dinv [3 * NN];
__device__ int   g_deg  [3 * NN];
__device__ int   g_off  [NN];
__device__ int   g_cur  [NN];
__device__ int   g_bsum [512];
__device__ int   g_csrc [EMAX];
__device__ float g_coefA[EMAX];
__device__ float g_coefM[EMAX];

__device__ __forceinline__ uint32_t smem_to_u32(const void* p) {
    uint32_t a;
    asm("{ .reg .u64 t; cvta.to.shared.u64 t, %1; cvt.u32.u64 %0, t; }" : "=r"(a) : "l"(p));
    return a;
}

// ---------------- bf16 split helper ----------------
__device__ __forceinline__ void split4(float4 v, __nv_bfloat16* hi, __nv_bfloat16* lo, size_t idx) {
    __nv_bfloat16 hx = __float2bfloat16(v.x), hy = __float2bfloat16(v.y);
    __nv_bfloat16 hz = __float2bfloat16(v.z), hw = __float2bfloat16(v.w);
    __nv_bfloat16 lx = __float2bfloat16(v.x - __bfloat162float(hx));
    __nv_bfloat16 ly = __float2bfloat16(v.y - __bfloat162float(hy));
    __nv_bfloat16 lz = __float2bfloat16(v.z - __bfloat162float(hz));
    __nv_bfloat16 lw = __float2bfloat16(v.w - __bfloat162float(hw));
    ((__nv_bfloat162*)(hi + idx))[0] = __nv_bfloat162(hx, hy);
    ((__nv_bfloat162*)(hi + idx))[1] = __nv_bfloat162(hz, hw);
    ((__nv_bfloat162*)(lo + idx))[0] = __nv_bfloat162(lx, ly);
    ((__nv_bfloat162*)(lo + idx))[1] = __nv_bfloat162(lz, lw);
}

// ---------------- CSR build ----------------
__global__ void zero_deg() {
    int i = blockIdx.x * blockDim.x + threadIdx.x;
    if (i < 3 * NN) g_deg[i] = 0;
}
__global__ void deg_kernel(const int* __restrict__ dst, const int* __restrict__ rev, int E) {
    int e = blockIdx.x * blockDim.x + threadIdx.x;
    if (e >= E) return;
    int d = dst[e];
    atomicAdd(&g_deg[2 * NN + d], 1);
    atomicAdd(&g_deg[(rev[e] ? NN : 0) + d], 1);
}
__global__ void dinv_kernel() {
    int i = blockIdx.x * blockDim.x + threadIdx.x;
    if (i < 3 * NN) g_dinv[i] = rsqrtf((float)g_deg[i] + 1.0f);
}
__global__ void scan_block() {
    __shared__ int sh[256];
    int tid = threadIdx.x;
    int i = blockIdx.x * 256 + tid;
    int v = (i < NN) ? g_deg[2 * NN + i] : 0;
    sh[tid] = v;
    __syncthreads();
    #pragma unroll
    for (int off = 1; off < 256; off <<= 1) {
        int t = (tid >= off) ? sh[tid - off] : 0;
        __syncthreads();
        sh[tid] += t;
        __syncthreads();
    }
    if (i < NN) g_off[i] = sh[tid] - v;
    if (tid == 255) g_bsum[blockIdx.x] = sh[255];
}
__global__ void scan_partials(int nb) {
    __shared__ int sh[512];
    int tid = threadIdx.x;
    int v = (tid < nb) ? g_bsum[tid] : 0;
    sh[tid] = v;
    __syncthreads();
    #pragma unroll
    for (int off = 1; off < 512; off <<= 1) {
        int t = (tid >= off) ? sh[tid - off] : 0;
        __syncthreads();
        sh[tid] += t;
        __syncthreads();
    }
    if (tid < nb) g_bsum[tid] = sh[tid] - v;
}
__global__ void scan_add() {
    int i = blockIdx.x * blockDim.x + threadIdx.x;
    if (i >= NN) return;
    int o = g_off[i] + g_bsum[i >> 8];
    g_off[i] = o;
    g_cur[i] = o;
}
__global__ void fill_csr(const int* __restrict__ src, const int* __restrict__ dst,
                         const int* __restrict__ rev, int E) {
    int e = blockIdx.x * blockDim.x + threadIdx.x;
    if (e >= E) return;
    int s = src[e], d = dst[e], r = rev[e];
    int pos = atomicAdd(&g_cur[d], 1);
    g_csrc[pos] = s | (r << 20);
    g_coefA[pos] = g_dinv[2 * NN + s] * g_dinv[2 * NN + d];
    const float* dv = g_dinv + (r ? NN : 0);
    g_coefM[pos] = dv[s] * dv[d];
}

// ---------------- split x into bf16 hi/lo ----------------
__global__ void split_x(const float* __restrict__ x) {
    long i = (long)blockIdx.x * blockDim.x + threadIdx.x;
    if (i >= (long)NN * F_IN / 4) return;
    float4 v = ((const float4*)x)[i];
    split4(v, g_xhi, g_xlo, (size_t)i * 4);
}

// ---------------- weight prep: transpose + split ----------------
__global__ void wprep1(const float* __restrict__ Wst, const float* __restrict__ Wts,
                       const float* __restrict__ W1f) {
    int i = blockIdx.x * blockDim.x + threadIdx.x;
    if (i >= 3 * 64 * F_IN) return;
    int t = i / (64 * F_IN);
    int n = (i / F_IN) % 64;
    int k = i % F_IN;
    const float* W = (t == 0) ? Wst : (t == 1) ? Wts : W1f;
    float v = W[k * 64 + n];
    __nv_bfloat16 h = __float2bfloat16(v);
    g_B1hi[i] = h;
    g_B1lo[i] = __float2bfloat16(v - __bfloat162float(h));
}
__global__ void wprep2(const float* __restrict__ W2) {
    int i = blockIdx.x * blockDim.x + threadIdx.x;
    if (i >= 2 * 64 * H1DIM) return;
    int t = i / (64 * H1DIM);
    int n = (i / H1DIM) % 64;
    int k = i % H1DIM;
    float v = W2[k * H2DIM + t * 64 + n];
    __nv_bfloat16 h = __float2bfloat16(v);
    g_B2hi[i] = h;
    g_B2lo[i] = __float2bfloat16(v - __bfloat162float(h));
}

// ================= mma.sync bf16-split GEMM =================
// C[M, NT*64] = A[M,K] @ B^T, A split hi/lo bf16 [M,K] row-major,
// B split tiles [t][64][K]. grid = (NT, ceil(M/128)). Block = 256 (8 warps).
// Warp w: (wm = w&3) m-subtile 32 rows, (wn = w>>2) n-subtile 32 cols.
// 3 passes fused per k-step: Ahi*Bhi + Ahi*Blo + Alo*Bhi, fp32 accumulate.

__device__ __forceinline__ void ldsm_x4(uint32_t* r, uint32_t addr) {
    asm volatile("ldmatrix.sync.aligned.m8n8.x4.shared.b16 {%0,%1,%2,%3}, [%4];"
                 : "=r"(r[0]), "=r"(r[1]), "=r"(r[2]), "=r"(r[3]) : "r"(addr));
}
__device__ __forceinline__ void mma_bf16(float* c, const uint32_t* a, const uint32_t* b) {
    asm volatile("mma.sync.aligned.m16n8k16.row.col.f32.bf16.bf16.f32 "
                 "{%0,%1,%2,%3}, {%4,%5,%6,%7}, {%8,%9}, {%0,%1,%2,%3};"
                 : "+f"(c[0]), "+f"(c[1]), "+f"(c[2]), "+f"(c[3])
                 : "r"(a[0]), "r"(a[1]), "r"(a[2]), "r"(a[3]), "r"(b[0]), "r"(b[1]));
}

__global__ void __launch_bounds__(256, 1)
mma_gemm(const __nv_bfloat16* __restrict__ Ahi, const __nv_bfloat16* __restrict__ Alo,
         const __nv_bfloat16* __restrict__ Bhi, const __nv_bfloat16* __restrict__ Blo,
         float* __restrict__ C, int M, int K, int NT) {
    extern __shared__ char smem[];
    const int lda = K + 8;                 // padded row (bf16 elems) -> conflict-free ldmatrix
    const uint32_t sAhi = 0;
    const uint32_t sAlo = sAhi + 128 * lda * 2;
    const uint32_t sBhi = sAlo + 128 * lda * 2;
    const uint32_t sBlo = sBhi + 64 * lda * 2;
    const uint32_t sbase = smem_to_u32(smem);

    const int tid = threadIdx.x;
    const int mb = blockIdx.y * 128;
    const int bx = blockIdx.x;             // n-tile
    const int kc8 = K / 8;

    // ---- stage A hi/lo (zero-fill rows >= M) ----
    for (int idx = tid; idx < 128 * kc8; idx += 256) {
        int ml = idx / kc8;
        int k0 = (idx % kc8) * 8;
        int row = mb + ml;
        uint4 vh = make_uint4(0, 0, 0, 0), vl = make_uint4(0, 0, 0, 0);
        if (row < M) {
            vh = *(const uint4*)(Ahi + (size_t)row * K + k0);
            vl = *(const uint4*)(Alo + (size_t)row * K + k0);
        }
        uint32_t off = (uint32_t)(ml * lda + k0) * 2;
        *(uint4*)(smem + sAhi + off) = vh;
        *(uint4*)(smem + sAlo + off) = vl;
    }
    // ---- stage this CTA's B tile hi/lo ----
    const __nv_bfloat16* Bht = Bhi + (size_t)bx * 64 * K;
    const __nv_bfloat16* Blt = Blo + (size_t)bx * 64 * K;
    for (int idx = tid; idx < 64 * kc8; idx += 256) {
        int nl = idx / kc8;
        int k0 = (idx % kc8) * 8;
        uint4 vh = *(const uint4*)(Bht + (size_t)nl * K + k0);
        uint4 vl = *(const uint4*)(Blt + (size_t)nl * K + k0);
        uint32_t off = (uint32_t)(nl * lda + k0) * 2;
        *(uint4*)(smem + sBhi + off) = vh;
        *(uint4*)(smem + sBlo + off) = vl;
    }
    __syncthreads();

    const int warp = tid >> 5;
    const int lane = tid & 31;
    const int wm = (warp & 3) * 32;        // warp m-offset in tile
    const int wn = (warp >> 2) * 32;       // warp n-offset in tile

    float c[2][4][4];
    #pragma unroll
    for (int mi = 0; mi < 2; mi++)
        #pragma unroll
        for (int ni = 0; ni < 4; ni++)
            #pragma unroll
            for (int j = 0; j < 4; j++) c[mi][ni][j] = 0.f;

    // ldmatrix lane address components
    const int a_m = wm + (lane & 15);          // + mi*16
    const int a_k = (lane >> 4) * 8;           // + k0
    const int b_n = wn + ((lane >> 4) & 1) * 8 + (lane & 7);  // + ni2*16
    const int b_k = ((lane >> 3) & 1) * 8;     // + k0

    for (int k0 = 0; k0 < K; k0 += 16) {
        uint32_t ah[2][4], al[2][4];
        #pragma unroll
        for (int mi = 0; mi < 2; mi++) {
            uint32_t off = (uint32_t)((a_m + mi * 16) * lda + k0 + a_k) * 2;
            ldsm_x4(ah[mi], sbase + sAhi + off);
            ldsm_x4(al[mi], sbase + sAlo + off);
        }
        // B: each x4 covers two n-frags (n..n+7, n+8..n+15) for both k halves
        uint32_t bh[4][2], bl[4][2];
        #pragma unroll
        for (int ni2 = 0; ni2 < 2; ni2++) {
            uint32_t tmp[4];
            uint32_t off = (uint32_t)((b_n + ni2 * 16) * lda + k0 + b_k) * 2;
            ldsm_x4(tmp, sbase + sBhi + off);
            bh[ni2 * 2 + 0][0] = tmp[0]; bh[ni2 * 2 + 0][1] = tmp[1];
            bh[ni2 * 2 + 1][0] = tmp[2]; bh[ni2 * 2 + 1][1] = tmp[3];
            ldsm_x4(tmp, sbase + sBlo + off);
            bl[ni2 * 2 + 0][0] = tmp[0]; bl[ni2 * 2 + 0][1] = tmp[1];
            bl[ni2 * 2 + 1][0] = tmp[2]; bl[ni2 * 2 + 1][1] = tmp[3];
        }
        #pragma unroll
        for (int mi = 0; mi < 2; mi++)
            #pragma unroll
            for (int ni = 0; ni < 4; ni++) {
                mma_bf16(c[mi][ni], ah[mi], bh[ni]);
                mma_bf16(c[mi][ni], ah[mi], bl[ni]);
                mma_bf16(c[mi][ni], al[mi], bh[ni]);
            }
    }

    // ---- epilogue ----
    const int ldc = NT * 64;
    const int r0 = lane >> 2;              // 0..7
    const int c0 = (lane & 3) * 2;
    #pragma unroll
    for (int mi = 0; mi < 2; mi++) {
        #pragma unroll
        for (int ni = 0; ni < 4; ni++) {
            int gcol = bx * 64 + wn + ni * 8 + c0;
            int grow0 = mb + wm + mi * 16 + r0;
            int grow1 = grow0 + 8;
            if (grow0 < M) {
                float2 v = make_float2(c[mi][ni][0], c[mi][ni][1]);
                *(float2*)(C + (size_t)grow0 * ldc + gcol) = v;
            }
            if (grow1 < M) {
                float2 v = make_float2(c[mi][ni][2], c[mi][ni][3]);
                *(float2*)(C + (size_t)grow1 * ldc + gcol) = v;
            }
        }
    }
}

// ---------------- fp32 SGEMM (layer 3 only) ----------------
__global__ void __launch_bounds__(256)
sgemm_kernel(const float* __restrict__ A, const float* __restrict__ B,
             float* __restrict__ C, int M, int Nc, int K, int ldc) {
    const int BM = 128, BK = 16;
    __shared__ float As[BK][BM];
    __shared__ float Bs[BK][64];
    int tid = threadIdx.x;
    int rowBlock = blockIdx.y * BM;
    int colBlock = blockIdx.x * 64;
    int tr = tid >> 4, tc = tid & 15;
    float acc[8][4];
    #pragma unroll
    for (int i = 0; i < 8; i++)
        #pragma unroll
        for (int j = 0; j < 4; j++) acc[i][j] = 0.f;
    int arow = tid >> 2, acol = (tid & 3) << 2;
    int brow = tid >> 4, bcol = (tid & 15) << 2;
    for (int k0 = 0; k0 < K; k0 += BK) {
        #pragma unroll
        for (int h = 0; h < 2; h++) {
            int r = arow + h * 64;
            int grow = rowBlock + r;
            float4 va = make_float4(0.f, 0.f, 0.f, 0.f);
            if (grow < M) va = *(const float4*)(A + (size_t)grow * K + k0 + acol);
            As[acol + 0][r] = va.x; As[acol + 1][r] = va.y;
            As[acol + 2][r] = va.z; As[acol + 3][r] = va.w;
        }
        {
            int gcol = colBlock + bcol;
            float t0 = (gcol + 0 < Nc) ? B[(size_t)(k0 + brow) * Nc + gcol + 0] : 0.f;
            float t1 = (gcol + 1 < Nc) ? B[(size_t)(k0 + brow) * Nc + gcol + 1] : 0.f;
            float t2 = (gcol + 2 < Nc) ? B[(size_t)(k0 + brow) * Nc + gcol + 2] : 0.f;
            float t3 = (gcol + 3 < Nc) ? B[(size_t)(k0 + brow) * Nc + gcol + 3] : 0.f;
            Bs[brow][bcol + 0] = t0; Bs[brow][bcol + 1] = t1;
            Bs[brow][bcol + 2] = t2; Bs[brow][bcol + 3] = t3;
        }
        __syncthreads();
        #pragma unroll
        for (int kk = 0; kk < BK; kk++) {
            float a[8], b[4];
            #pragma unroll
            for (int i = 0; i < 8; i++) a[i] = As[kk][tr * 8 + i];
            #pragma unroll
            for (int j = 0; j < 4; j++) b[j] = Bs[kk][tc * 4 + j];
            #pragma unroll
            for (int i = 0; i < 8; i++)
                #pragma unroll
                for (int j = 0; j < 4; j++) acc[i][j] += a[i] * b[j];
        }
        __syncthreads();
    }
    #pragma unroll
    for (int i = 0; i < 8; i++) {
        int grow = rowBlock + tr * 8 + i;
        if (grow >= M) continue;
        #pragma unroll
        for (int j = 0; j < 4; j++) {
            int gcol = colBlock + tc * 4 + j;
            if (gcol < Nc) C[(size_t)grow * ldc + gcol] = acc[i][j];
        }
    }
}

// ---------------- layer-1 CSR gather (writes split bf16 h1) ----------------
__global__ void gather1(const float* __restrict__ b_st, const float* __restrict__ b_ts,
                        const float* __restrict__ b1) {
    int node = blockIdx.x * (blockDim.x >> 5) + (threadIdx.x >> 5);
    if (node >= NN) return;
    int lane = threadIdx.x & 31;
    int beg = g_off[node];
    int end = beg + g_deg[2 * NN + node];

    float4 accS = make_float4(0.f, 0.f, 0.f, 0.f);
    float4 accT = make_float4(0.f, 0.f, 0.f, 0.f);
    float4 accA = make_float4(0.f, 0.f, 0.f, 0.f);

    for (int base = beg; base < end; base += 32) {
        int n = min(32, end - base);
        int msrc = 0; float mca = 0.f, mcm = 0.f;
        if (lane < n) {
            msrc = g_csrc[base + lane];
            mca  = g_coefA[base + lane];
            mcm  = g_coefM[base + lane];
        }
        for (int j = 0; j < n; j++) {
            int sp   = __shfl_sync(0xFFFFFFFFu, msrc, j);
            float ca = __shfl_sync(0xFFFFFFFFu, mca, j);
            float cm = __shfl_sync(0xFFFFFFFFu, mcm, j);
            int s = sp & 0xFFFFF;
            int r = sp >> 20;
            if (lane < 16) {
                float4 v = *(const float4*)(g_hlin + (size_t)s * H1DIM + (r ? 64 : 0) + lane * 4);
                if (r) { accT.x += v.x * cm; accT.y += v.y * cm; accT.z += v.z * cm; accT.w += v.w * cm; }
                else   { accS.x += v.x * cm; accS.y += v.y * cm; accS.z += v.z * cm; accS.w += v.w * cm; }
            } else {
                float4 v = *(const float4*)(g_hlin + (size_t)s * H1DIM + 128 + (lane - 16) * 4);
                accA.x += v.x * ca; accA.y += v.y * ca; accA.z += v.z * ca; accA.w += v.w * ca;
            }
        }
    }

    float dvS = g_dinv[node], dvT = g_dinv[NN + node], dvA = g_dinv[2 * NN + node];
    const float* hrow = g_hlin + (size_t)node * H1DIM;
    size_t obase = (size_t)node * H1DIM;
    if (lane < 16) {
        int c = lane * 4;
        float sS = dvS * dvS;
        float4 h = *(const float4*)(hrow + c);
        float4 bb = *(const float4*)(b_st + c);
        float4 o;
        o.x = fmaxf(accS.x + h.x * sS + bb.x, 0.f);
        o.y = fmaxf(accS.y + h.y * sS + bb.y, 0.f);
        o.z = fmaxf(accS.z + h.z * sS + bb.z, 0.f);
        o.w = fmaxf(accS.w + h.w * sS + bb.w, 0.f);
        split4(o, g_h1hi, g_h1lo, obase + c);

        float sT = dvT * dvT;
        h = *(const float4*)(hrow + 64 + c);
        bb = *(const float4*)(b_ts + c);
        o.x = fmaxf(accT.x + h.x * sT + bb.x, 0.f);
        o.y = fmaxf(accT.y + h.y * sT + bb.y, 0.f);
        o.z = fmaxf(accT.z + h.z * sT + bb.z, 0.f);
        o.w = fmaxf(accT.w + h.w * sT + bb.w, 0.f);
        split4(o, g_h1hi, g_h1lo, obase + 64 + c);
    } else {
        int c = (lane - 16) * 4;
        float sA = dvA * dvA;
        float4 h = *(const float4*)(hrow + 128 + c);
        float4 bb = *(const float4*)(b1 + c);
        float4 o;
        o.x = fmaxf(accA.x + h.x * sA + bb.x, 0.f);
        o.y = fmaxf(accA.y + h.y * sA + bb.y, 0.f);
        o.z = fmaxf(accA.z + h.z * sA + bb.z, 0.f);
        o.w = fmaxf(accA.w + h.w * sA + bb.w, 0.f);
        split4(o, g_h1hi, g_h1lo, obase + 128 + c);
    }
}

// ---------------- layer-2 CSR gather ----------------
__global__ void gather2(const float* __restrict__ b2) {
    int node = blockIdx.x * (blockDim.x >> 5) + (threadIdx.x >> 5);
    if (node >= NN) return;
    int lane = threadIdx.x & 31;
    int beg = g_off[node];
    int end = beg + g_deg[2 * NN + node];

    float4 acc = make_float4(0.f, 0.f, 0.f, 0.f);
    for (int base = beg; base < end; base += 32) {
        int n = min(32, end - base);
        int msrc = 0; float mca = 0.f;
        if (lane < n) {
            msrc = g_csrc[base + lane];
            mca  = g_coefA[base + lane];
        }
        for (int j = 0; j < n; j++) {
            int sp   = __shfl_sync(0xFFFFFFFFu, msrc, j);
            float ca = __shfl_sync(0xFFFFFFFFu, mca, j);
            int s = sp & 0xFFFFF;
            float4 v = ((const float4*)(g_h2lin + (size_t)s * H2DIM))[lane];
            acc.x += v.x * ca; acc.y += v.y * ca; acc.z += v.z * ca; acc.w += v.w * ca;
        }
    }
    float dv = g_dinv[2 * NN + node];
    float self = dv * dv;
    int c = lane * 4;
    float4 h = *(const float4*)(g_h2lin + (size_t)node * H2DIM + c);
    float4 bb = *(const float4*)(b2 + c);
    float4 o;
    o.x = acc.x + h.x * self + bb.x;
    o.y = acc.y + h.y * self + bb.y;
    o.z = acc.z + h.z * self + bb.z;
    o.w = acc.w + h.w * self + bb.w;
    *(float4*)(g_h2 + (size_t)node * H2DIM + c) = o;
}

// ---------------- layer-3 CSR gather + log_softmax ----------------
__global__ void gather3(float* __restrict__ out, const float* __restrict__ b3) {
    int node = blockIdx.x * (blockDim.x >> 5) + (threadIdx.x >> 5);
    if (node >= NN) return;
    int lane = threadIdx.x & 31;
    int half = lane >> 4;
    int l16 = lane & 15;
    int beg = g_off[node];
    int end = beg + g_deg[2 * NN + node];

    float acc = 0.f;
    for (int idx = beg + half; idx < end; idx += 2) {
        int sp = g_csrc[idx];
        float ca = g_coefA[idx];
        int s = sp & 0xFFFFF;
        acc += g_h3lin[(size_t)s * NCLS + l16] * ca;
    }
    acc += __shfl_down_sync(0xFFFFFFFFu, acc, 16);

    float dv = g_dinv[2 * NN + node];
    float self = dv * dv;
    float v = acc + g_h3lin[(size_t)node * NCLS + l16] * self + b3[l16];

    float m = v;
    #pragma unroll
    for (int o = 8; o > 0; o >>= 1) m = fmaxf(m, __shfl_xor_sync(0xFFFFFFFFu, m, o, 16));
    float s = expf(v - m);
    #pragma unroll
    for (int o = 8; o > 0; o >>= 1) s += __shfl_xor_sync(0xFFFFFFFFu, s, o, 16);
    float l = logf(s);
    if (lane < 16) out[(size_t)node * NCLS + l16] = v - m - l;
}

// ---------------- host launcher ----------------
extern "C" void kernel_launch(void* const* d_in, const int* in_sizes, int n_in,
                              void* d_out, int out_size) {
    const float* x    = (const float*)d_in[0];
    const int*   eidx = (const int*)d_in[1];
    const int    E    = in_sizes[1] / 2;
    const int*   src  = eidx;
    const int*   dst  = eidx + E;
    const int*   rev  = (const int*)d_in[2];
    const float* W_st = (const float*)d_in[3];
    const float* b_st = (const float*)d_in[4];
    const float* W_ts = (const float*)d_in[5];
    const float* b_ts = (const float*)d_in[6];
    const float* W1   = (const float*)d_in[7];
    const float* b1   = (const float*)d_in[8];
    const float* W2   = (const float*)d_in[9];
    const float* b2   = (const float*)d_in[10];
    const float* W3   = (const float*)d_in[11];
    const float* b3   = (const float*)d_in[12];
    float* out = (float*)d_out;

    float *hlin, *h2lin, *h2, *h3lin;
    __nv_bfloat16 *xhi, *xlo, *h1hi, *h1lo, *B1hi, *B1lo, *B2hi, *B2lo;
    cudaGetSymbolAddress((void**)&hlin,  g_hlin);
    cudaGetSymbolAddress((void**)&h2lin, g_h2lin);
    cudaGetSymbolAddress((void**)&h2,    g_h2);
    cudaGetSymbolAddress((void**)&h3lin, g_h3lin);
    cudaGetSymbolAddress((void**)&xhi,   g_xhi);
    cudaGetSymbolAddress((void**)&xlo,   g_xlo);
    cudaGetSymbolAddress((void**)&h1hi,  g_h1hi);
    cudaGetSymbolAddress((void**)&h1lo,  g_h1lo);
    cudaGetSymbolAddress((void**)&B1hi,  g_B1hi);
    cudaGetSymbolAddress((void**)&B1lo,  g_B1lo);
    cudaGetSymbolAddress((void**)&B2hi,  g_B2hi);
    cudaGetSymbolAddress((void**)&B2lo,  g_B2lo);

    // max dynamic smem: layer2 => 384 rows * (192+8) elems * 2 B = 153600
    cudaFuncSetAttribute(mma_gemm, cudaFuncAttributeMaxDynamicSharedMemorySize, 160000);

    const int nb = (NN + 255) / 256;

    // ---- CSR + normalization build ----
    zero_deg<<<(3 * NN + 255) / 256, 256>>>();
    deg_kernel<<<(E + 255) / 256, 256>>>(dst, rev, E);
    dinv_kernel<<<(3 * NN + 255) / 256, 256>>>();
    scan_block<<<nb, 256>>>();
    scan_partials<<<1, 512>>>(nb);
    scan_add<<<nb, 256>>>();
    fill_csr<<<(E + 255) / 256, 256>>>(src, dst, rev, E);

    // ---- operand prep ----
    split_x<<<((NN * F_IN / 4) + 255) / 256, 256>>>(x);
    wprep1<<<(3 * 64 * F_IN + 255) / 256, 256>>>(W_st, W_ts, W1);
    wprep2<<<(2 * 64 * H1DIM + 255) / 256, 256>>>(W2);

    const int gblocks = (NN + 127) / 128;   // 782

    // ---- layer 1: [100k,128] @ [128,192] via bf16-split MMA ----
    {
        int smem = 384 * (F_IN + 8) * 2;    // 104448
        mma_gemm<<<dim3(3, gblocks), 256, smem>>>(xhi, xlo, B1hi, B1lo, hlin, NN, F_IN, 3);
    }
    gather1<<<(NN * 32 + 255) / 256, 256>>>(b_st, b_ts, b1);

    // ---- layer 2: [100k,192] @ [192,128] ----
    {
        int smem = 384 * (H1DIM + 8) * 2;   // 153600
        mma_gemm<<<dim3(2, gblocks), 256, smem>>>(h1hi, h1lo, B2hi, B2lo, h2lin, NN, H1DIM, 2);
    }
    gather2<<<(NN * 32 + 255) / 256, 256>>>(b2);

    // ---- layer 3 (fp32 SGEMM, tiny) ----
    dim3 g3(1, gblocks);
    sgemm_kernel<<<g3, 256>>>(h2, W3, h3lin, NN, NCLS, H2DIM, NCLS);
    gather3<<<(NN * 32 + 255) / 256, 256>>>(out, b3);
}

// round 5
// speedup vs baseline: 1.7444x; 1.0814x over previous
#include <cuda_runtime.h>
#include <cuda_bf16.h>
#include <cuda_fp16.h>
#include <math.h>
#include <cstdint>

#define NN    100000
#define F_IN  128
#define H1DIM 192     // 64 st + 64 ts + 64 all
#define H2DIM 128
#define NCLS  16
#define EMAX  1600000

// ---------------- device scratch (static, no allocation) ----------------
__device__ __half g_hlin16 [(size_t)NN * H1DIM];  // x @ [W_st|W_ts|W1]  (fp16)
__device__ __nv_bfloat16 g_h1hi[(size_t)NN * H1DIM];  // h1 split hi (GEMM2 A input)
__device__ __nv_bfloat16 g_h1lo[(size_t)NN * H1DIM];  // h1 split lo
__device__ __half g_h2lin16[(size_t)NN * H2DIM]; // h1 @ W2 (fp16)
__device__ float  g_h2   [(size_t)NN * H2DIM];   // gcn layer2 (fp32, sgemm3 input)
__device__ float  g_h3lin[(size_t)NN * NCLS];    // h2 @ W3
__device__ __nv_bfloat16 g_xhi[(size_t)NN * F_IN];
__device__ __nv_bfloat16 g_xlo[(size_t)NN * F_IN];
__device__ __nv_bfloat16 g_B1hi[3 * 64 * F_IN];   // W1cat^T tiles [t][n][k]
__device__ __nv_bfloat16 g_B1lo[3 * 64 * F_IN];
__device__ __nv_bfloat16 g_B2hi[2 * 64 * H1DIM];  // W2^T tiles
__device__ __nv_bfloat16 g_B2lo[2 * 64 * H1DIM];
__device__ float g_dinv [3 * NN];
__device__ int   g_deg  [3 * NN];
__device__ int   g_off  [NN];
__device__ int   g_cur  [NN];
__device__ int   g_bsum [512];
__device__ int   g_csrc [EMAX];
__device__ float g_coefA[EMAX];
__device__ float g_coefM[EMAX];

__device__ __forceinline__ uint32_t smem_to_u32(const void* p) {
    uint32_t a;
    asm("{ .reg .u64 t; cvta.to.shared.u64 t, %1; cvt.u32.u64 %0, t; }" : "=r"(a) : "l"(p));
    return a;
}

// ---------------- bf16 split helper ----------------
__device__ __forceinline__ void split4(float4 v, __nv_bfloat16* hi, __nv_bfloat16* lo, size_t idx) {
    __nv_bfloat16 hx = __float2bfloat16(v.x), hy = __float2bfloat16(v.y);
    __nv_bfloat16 hz = __float2bfloat16(v.z), hw = __float2bfloat16(v.w);
    __nv_bfloat16 lx = __float2bfloat16(v.x - __bfloat162float(hx));
    __nv_bfloat16 ly = __float2bfloat16(v.y - __bfloat162float(hy));
    __nv_bfloat16 lz = __float2bfloat16(v.z - __bfloat162float(hz));
    __nv_bfloat16 lw = __float2bfloat16(v.w - __bfloat162float(hw));
    ((__nv_bfloat162*)(hi + idx))[0] = __nv_bfloat162(hx, hy);
    ((__nv_bfloat162*)(hi + idx))[1] = __nv_bfloat162(hz, hw);
    ((__nv_bfloat162*)(lo + idx))[0] = __nv_bfloat162(lx, ly);
    ((__nv_bfloat162*)(lo + idx))[1] = __nv_bfloat162(lz, lw);
}

// fp16 4-value load -> float4
__device__ __forceinline__ float4 ldh4(const __half* p) {
    uint2 u = *(const uint2*)p;
    __half2 p0 = *reinterpret_cast<__half2*>(&u.x);
    __half2 p1 = *reinterpret_cast<__half2*>(&u.y);
    float2 f0 = __half22float2(p0);
    float2 f1 = __half22float2(p1);
    return make_float4(f0.x, f0.y, f1.x, f1.y);
}

// ---------------- CSR build ----------------
__global__ void zero_deg() {
    int i = blockIdx.x * blockDim.x + threadIdx.x;
    if (i < 3 * NN) g_deg[i] = 0;
}
__global__ void deg_kernel(const int* __restrict__ dst, const int* __restrict__ rev, int E) {
    int e = blockIdx.x * blockDim.x + threadIdx.x;
    if (e >= E) return;
    int d = dst[e];
    atomicAdd(&g_deg[2 * NN + d], 1);
    atomicAdd(&g_deg[(rev[e] ? NN : 0) + d], 1);
}
__global__ void scan_block() {
    __shared__ int sh[256];
    int tid = threadIdx.x;
    int i = blockIdx.x * 256 + tid;
    int v = (i < NN) ? g_deg[2 * NN + i] : 0;
    sh[tid] = v;
    __syncthreads();
    #pragma unroll
    for (int off = 1; off < 256; off <<= 1) {
        int t = (tid >= off) ? sh[tid - off] : 0;
        __syncthreads();
        sh[tid] += t;
        __syncthreads();
    }
    if (i < NN) g_off[i] = sh[tid] - v;
    if (tid == 255) g_bsum[blockIdx.x] = sh[255];
}
__global__ void scan_partials(int nb) {
    __shared__ int sh[512];
    int tid = threadIdx.x;
    int v = (tid < nb) ? g_bsum[tid] : 0;
    sh[tid] = v;
    __syncthreads();
    #pragma unroll
    for (int off = 1; off < 512; off <<= 1) {
        int t = (tid >= off) ? sh[tid - off] : 0;
        __syncthreads();
        sh[tid] += t;
        __syncthreads();
    }
    if (tid < nb) g_bsum[tid] = sh[tid] - v;
}
// fused: dinv for all 3*NN entries + offset/cursor finalize for NN entries
__global__ void scan_add_dinv() {
    int i = blockIdx.x * blockDim.x + threadIdx.x;
    if (i >= 3 * NN) return;
    g_dinv[i] = rsqrtf((float)g_deg[i] + 1.0f);
    if (i < NN) {
        int o = g_off[i] + g_bsum[i >> 8];
        g_off[i] = o;
        g_cur[i] = o;
    }
}
__global__ void fill_csr(const int* __restrict__ src, const int* __restrict__ dst,
                         const int* __restrict__ rev, int E) {
    int e = blockIdx.x * blockDim.x + threadIdx.x;
    if (e >= E) return;
    int s = src[e], d = dst[e], r = rev[e];
    int pos = atomicAdd(&g_cur[d], 1);
    g_csrc[pos] = s | (r << 20);
    g_coefA[pos] = g_dinv[2 * NN + s] * g_dinv[2 * NN + d];
    const float* dv = g_dinv + (r ? NN : 0);
    g_coefM[pos] = dv[s] * dv[d];
}

// ---------------- split x into bf16 hi/lo ----------------
__global__ void split_x(const float* __restrict__ x) {
    long i = (long)blockIdx.x * blockDim.x + threadIdx.x;
    if (i >= (long)NN * F_IN / 4) return;
    float4 v = ((const float4*)x)[i];
    split4(v, g_xhi, g_xlo, (size_t)i * 4);
}

// ---------------- weight prep: transpose + split ----------------
__global__ void wprep1(const float* __restrict__ Wst, const float* __restrict__ Wts,
                       const float* __restrict__ W1f) {
    int i = blockIdx.x * blockDim.x + threadIdx.x;
    if (i >= 3 * 64 * F_IN) return;
    int t = i / (64 * F_IN);
    int n = (i / F_IN) % 64;
    int k = i % F_IN;
    const float* W = (t == 0) ? Wst : (t == 1) ? Wts : W1f;
    float v = W[k * 64 + n];
    __nv_bfloat16 h = __float2bfloat16(v);
    g_B1hi[i] = h;
    g_B1lo[i] = __float2bfloat16(v - __bfloat162float(h));
}
__global__ void wprep2(const float* __restrict__ W2) {
    int i = blockIdx.x * blockDim.x + threadIdx.x;
    if (i >= 2 * 64 * H1DIM) return;
    int t = i / (64 * H1DIM);
    int n = (i / H1DIM) % 64;
    int k = i % H1DIM;
    float v = W2[k * H2DIM + t * 64 + n];
    __nv_bfloat16 h = __float2bfloat16(v);
    g_B2hi[i] = h;
    g_B2lo[i] = __float2bfloat16(v - __bfloat162float(h));
}

// ================= mma.sync bf16-split GEMM =================
// C[M, NT*64] = A[M,K] @ B^T, output fp16.
__device__ __forceinline__ void ldsm_x4(uint32_t* r, uint32_t addr) {
    asm volatile("ldmatrix.sync.aligned.m8n8.x4.shared.b16 {%0,%1,%2,%3}, [%4];"
                 : "=r"(r[0]), "=r"(r[1]), "=r"(r[2]), "=r"(r[3]) : "r"(addr));
}
__device__ __forceinline__ void mma_bf16(float* c, const uint32_t* a, const uint32_t* b) {
    asm volatile("mma.sync.aligned.m16n8k16.row.col.f32.bf16.bf16.f32 "
                 "{%0,%1,%2,%3}, {%4,%5,%6,%7}, {%8,%9}, {%0,%1,%2,%3};"
                 : "+f"(c[0]), "+f"(c[1]), "+f"(c[2]), "+f"(c[3])
                 : "r"(a[0]), "r"(a[1]), "r"(a[2]), "r"(a[3]), "r"(b[0]), "r"(b[1]));
}

__global__ void __launch_bounds__(256, 1)
mma_gemm(const __nv_bfloat16* __restrict__ Ahi, const __nv_bfloat16* __restrict__ Alo,
         const __nv_bfloat16* __restrict__ Bhi, const __nv_bfloat16* __restrict__ Blo,
         __half* __restrict__ C, int M, int K, int NT) {
    extern __shared__ char smem[];
    const int lda = K + 8;                 // padded row -> conflict-free ldmatrix
    const uint32_t sAhi = 0;
    const uint32_t sAlo = sAhi + 128 * lda * 2;
    const uint32_t sBhi = sAlo + 128 * lda * 2;
    const uint32_t sBlo = sBhi + 64 * lda * 2;
    const uint32_t sbase = smem_to_u32(smem);

    const int tid = threadIdx.x;
    const int mb = blockIdx.y * 128;
    const int bx = blockIdx.x;             // n-tile
    const int kc8 = K / 8;

    for (int idx = tid; idx < 128 * kc8; idx += 256) {
        int ml = idx / kc8;
        int k0 = (idx % kc8) * 8;
        int row = mb + ml;
        uint4 vh = make_uint4(0, 0, 0, 0), vl = make_uint4(0, 0, 0, 0);
        if (row < M) {
            vh = *(const uint4*)(Ahi + (size_t)row * K + k0);
            vl = *(const uint4*)(Alo + (size_t)row * K + k0);
        }
        uint32_t off = (uint32_t)(ml * lda + k0) * 2;
        *(uint4*)(smem + sAhi + off) = vh;
        *(uint4*)(smem + sAlo + off) = vl;
    }
    const __nv_bfloat16* Bht = Bhi + (size_t)bx * 64 * K;
    const __nv_bfloat16* Blt = Blo + (size_t)bx * 64 * K;
    for (int idx = tid; idx < 64 * kc8; idx += 256) {
        int nl = idx / kc8;
        int k0 = (idx % kc8) * 8;
        uint4 vh = *(const uint4*)(Bht + (size_t)nl * K + k0);
        uint4 vl = *(const uint4*)(Blt + (size_t)nl * K + k0);
        uint32_t off = (uint32_t)(nl * lda + k0) * 2;
        *(uint4*)(smem + sBhi + off) = vh;
        *(uint4*)(smem + sBlo + off) = vl;
    }
    __syncthreads();

    const int warp = tid >> 5;
    const int lane = tid & 31;
    const int wm = (warp & 3) * 32;
    const int wn = (warp >> 2) * 32;

    float c[2][4][4];
    #pragma unroll
    for (int mi = 0; mi < 2; mi++)
        #pragma unroll
        for (int ni = 0; ni < 4; ni++)
            #pragma unroll
            for (int j = 0; j < 4; j++) c[mi][ni][j] = 0.f;

    const int a_m = wm + (lane & 15);
    const int a_k = (lane >> 4) * 8;
    const int b_n = wn + ((lane >> 4) & 1) * 8 + (lane & 7);
    const int b_k = ((lane >> 3) & 1) * 8;

    for (int k0 = 0; k0 < K; k0 += 16) {
        uint32_t ah[2][4], al[2][4];
        #pragma unroll
        for (int mi = 0; mi < 2; mi++) {
            uint32_t off = (uint32_t)((a_m + mi * 16) * lda + k0 + a_k) * 2;
            ldsm_x4(ah[mi], sbase + sAhi + off);
            ldsm_x4(al[mi], sbase + sAlo + off);
        }
        uint32_t bh[4][2], bl[4][2];
        #pragma unroll
        for (int ni2 = 0; ni2 < 2; ni2++) {
            uint32_t tmp[4];
            uint32_t off = (uint32_t)((b_n + ni2 * 16) * lda + k0 + b_k) * 2;
            ldsm_x4(tmp, sbase + sBhi + off);
            bh[ni2 * 2 + 0][0] = tmp[0]; bh[ni2 * 2 + 0][1] = tmp[1];
            bh[ni2 * 2 + 1][0] = tmp[2]; bh[ni2 * 2 + 1][1] = tmp[3];
            ldsm_x4(tmp, sbase + sBlo + off);
            bl[ni2 * 2 + 0][0] = tmp[0]; bl[ni2 * 2 + 0][1] = tmp[1];
            bl[ni2 * 2 + 1][0] = tmp[2]; bl[ni2 * 2 + 1][1] = tmp[3];
        }
        #pragma unroll
        for (int mi = 0; mi < 2; mi++)
            #pragma unroll
            for (int ni = 0; ni < 4; ni++) {
                mma_bf16(c[mi][ni], ah[mi], bh[ni]);
                mma_bf16(c[mi][ni], ah[mi], bl[ni]);
                mma_bf16(c[mi][ni], al[mi], bh[ni]);
            }
    }

    // ---- epilogue: fp16 stores ----
    const int ldc = NT * 64;
    const int r0 = lane >> 2;
    const int c0 = (lane & 3) * 2;
    #pragma unroll
    for (int mi = 0; mi < 2; mi++) {
        #pragma unroll
        for (int ni = 0; ni < 4; ni++) {
            int gcol = bx * 64 + wn + ni * 8 + c0;
            int grow0 = mb + wm + mi * 16 + r0;
            int grow1 = grow0 + 8;
            if (grow0 < M) {
                __half2 v = __floats2half2_rn(c[mi][ni][0], c[mi][ni][1]);
                *(__half2*)(C + (size_t)grow0 * ldc + gcol) = v;
            }
            if (grow1 < M) {
                __half2 v = __floats2half2_rn(c[mi][ni][2], c[mi][ni][3]);
                *(__half2*)(C + (size_t)grow1 * ldc + gcol) = v;
            }
        }
    }
}

// ---------------- fp32 SGEMM (layer 3 only) ----------------
__global__ void __launch_bounds__(256)
sgemm_kernel(const float* __restrict__ A, const float* __restrict__ B,
             float* __restrict__ C, int M, int Nc, int K, int ldc) {
    const int BM = 128, BK = 16;
    __shared__ float As[BK][BM];
    __shared__ float Bs[BK][64];
    int tid = threadIdx.x;
    int rowBlock = blockIdx.y * BM;
    int colBlock = blockIdx.x * 64;
    int tr = tid >> 4, tc = tid & 15;
    float acc[8][4];
    #pragma unroll
    for (int i = 0; i < 8; i++)
        #pragma unroll
        for (int j = 0; j < 4; j++) acc[i][j] = 0.f;
    int arow = tid >> 2, acol = (tid & 3) << 2;
    int brow = tid >> 4, bcol = (tid & 15) << 2;
    for (int k0 = 0; k0 < K; k0 += BK) {
        #pragma unroll
        for (int h = 0; h < 2; h++) {
            int r = arow + h * 64;
            int grow = rowBlock + r;
            float4 va = make_float4(0.f, 0.f, 0.f, 0.f);
            if (grow < M) va = *(const float4*)(A + (size_t)grow * K + k0 + acol);
            As[acol + 0][r] = va.x; As[acol + 1][r] = va.y;
            As[acol + 2][r] = va.z; As[acol + 3][r] = va.w;
        }
        {
            int gcol = colBlock + bcol;
            float t0 = (gcol + 0 < Nc) ? B[(size_t)(k0 + brow) * Nc + gcol + 0] : 0.f;
            float t1 = (gcol + 1 < Nc) ? B[(size_t)(k0 + brow) * Nc + gcol + 1] : 0.f;
            float t2 = (gcol + 2 < Nc) ? B[(size_t)(k0 + brow) * Nc + gcol + 2] : 0.f;
            float t3 = (gcol + 3 < Nc) ? B[(size_t)(k0 + brow) * Nc + gcol + 3] : 0.f;
            Bs[brow][bcol + 0] = t0; Bs[brow][bcol + 1] = t1;
            Bs[brow][bcol + 2] = t2; Bs[brow][bcol + 3] = t3;
        }
        __syncthreads();
        #pragma unroll
        for (int kk = 0; kk < BK; kk++) {
            float a[8], b[4];
            #pragma unroll
            for (int i = 0; i < 8; i++) a[i] = As[kk][tr * 8 + i];
            #pragma unroll
            for (int j = 0; j < 4; j++) b[j] = Bs[kk][tc * 4 + j];
            #pragma unroll
            for (int i = 0; i < 8; i++)
                #pragma unroll
                for (int j = 0; j < 4; j++) acc[i][j] += a[i] * b[j];
        }
        __syncthreads();
    }
    #pragma unroll
    for (int i = 0; i < 8; i++) {
        int grow = rowBlock + tr * 8 + i;
        if (grow >= M) continue;
        #pragma unroll
        for (int j = 0; j < 4; j++) {
            int gcol = colBlock + tc * 4 + j;
            if (gcol < Nc) C[(size_t)grow * ldc + gcol] = acc[i][j];
        }
    }
}

// ---------------- layer-1 CSR gather (fp16 in, split bf16 out) ----------------
__global__ void gather1(const float* __restrict__ b_st, const float* __restrict__ b_ts,
                        const float* __restrict__ b1) {
    int node = blockIdx.x * (blockDim.x >> 5) + (threadIdx.x >> 5);
    if (node >= NN) return;
    int lane = threadIdx.x & 31;
    int beg = g_off[node];
    int end = beg + g_deg[2 * NN + node];

    float4 accS = make_float4(0.f, 0.f, 0.f, 0.f);
    float4 accT = make_float4(0.f, 0.f, 0.f, 0.f);
    float4 accA = make_float4(0.f, 0.f, 0.f, 0.f);

    for (int base = beg; base < end; base += 32) {
        int n = min(32, end - base);
        int msrc = 0; float mca = 0.f, mcm = 0.f;
        if (lane < n) {
            msrc = g_csrc[base + lane];
            mca  = g_coefA[base + lane];
            mcm  = g_coefM[base + lane];
        }
        for (int j = 0; j < n; j++) {
            int sp   = __shfl_sync(0xFFFFFFFFu, msrc, j);
            float ca = __shfl_sync(0xFFFFFFFFu, mca, j);
            float cm = __shfl_sync(0xFFFFFFFFu, mcm, j);
            int s = sp & 0xFFFFF;
            int r = sp >> 20;
            if (lane < 16) {
                float4 v = ldh4(g_hlin16 + (size_t)s * H1DIM + (r ? 64 : 0) + lane * 4);
                if (r) { accT.x += v.x * cm; accT.y += v.y * cm; accT.z += v.z * cm; accT.w += v.w * cm; }
                else   { accS.x += v.x * cm; accS.y += v.y * cm; accS.z += v.z * cm; accS.w += v.w * cm; }
            } else {
                float4 v = ldh4(g_hlin16 + (size_t)s * H1DIM + 128 + (lane - 16) * 4);
                accA.x += v.x * ca; accA.y += v.y * ca; accA.z += v.z * ca; accA.w += v.w * ca;
            }
        }
    }

    float dvS = g_dinv[node], dvT = g_dinv[NN + node], dvA = g_dinv[2 * NN + node];
    const __half* hrow = g_hlin16 + (size_t)node * H1DIM;
    size_t obase = (size_t)node * H1DIM;
    if (lane < 16) {
        int c = lane * 4;
        float sS = dvS * dvS;
        float4 h = ldh4(hrow + c);
        float4 bb = *(const float4*)(b_st + c);
        float4 o;
        o.x = fmaxf(accS.x + h.x * sS + bb.x, 0.f);
        o.y = fmaxf(accS.y + h.y * sS + bb.y, 0.f);
        o.z = fmaxf(accS.z + h.z * sS + bb.z, 0.f);
        o.w = fmaxf(accS.w + h.w * sS + bb.w, 0.f);
        split4(o, g_h1hi, g_h1lo, obase + c);

        float sT = dvT * dvT;
        h = ldh4(hrow + 64 + c);
        bb = *(const float4*)(b_ts + c);
        o.x = fmaxf(accT.x + h.x * sT + bb.x, 0.f);
        o.y = fmaxf(accT.y + h.y * sT + bb.y, 0.f);
        o.z = fmaxf(accT.z + h.z * sT + bb.z, 0.f);
        o.w = fmaxf(accT.w + h.w * sT + bb.w, 0.f);
        split4(o, g_h1hi, g_h1lo, obase + 64 + c);
    } else {
        int c = (lane - 16) * 4;
        float sA = dvA * dvA;
        float4 h = ldh4(hrow + 128 + c);
        float4 bb = *(const float4*)(b1 + c);
        float4 o;
        o.x = fmaxf(accA.x + h.x * sA + bb.x, 0.f);
        o.y = fmaxf(accA.y + h.y * sA + bb.y, 0.f);
        o.z = fmaxf(accA.z + h.z * sA + bb.z, 0.f);
        o.w = fmaxf(accA.w + h.w * sA + bb.w, 0.f);
        split4(o, g_h1hi, g_h1lo, obase + 128 + c);
    }
}

// ---------------- layer-2 CSR gather (fp16 in, fp32 out) ----------------
__global__ void gather2(const float* __restrict__ b2) {
    int node = blockIdx.x * (blockDim.x >> 5) + (threadIdx.x >> 5);
    if (node >= NN) return;
    int lane = threadIdx.x & 31;
    int beg = g_off[node];
    int end = beg + g_deg[2 * NN + node];

    float4 acc = make_float4(0.f, 0.f, 0.f, 0.f);
    for (int base = beg; base < end; base += 32) {
        int n = min(32, end - base);
        int msrc = 0; float mca = 0.f;
        if (lane < n) {
            msrc = g_csrc[base + lane];
            mca  = g_coefA[base + lane];
        }
        for (int j = 0; j < n; j++) {
            int sp   = __shfl_sync(0xFFFFFFFFu, msrc, j);
            float ca = __shfl_sync(0xFFFFFFFFu, mca, j);
            int s = sp & 0xFFFFF;
            float4 v = ldh4(g_h2lin16 + (size_t)s * H2DIM + lane * 4);
            acc.x += v.x * ca; acc.y += v.y * ca; acc.z += v.z * ca; acc.w += v.w * ca;
        }
    }
    float dv = g_dinv[2 * NN + node];
    float self = dv * dv;
    int c = lane * 4;
    float4 h = ldh4(g_h2lin16 + (size_t)node * H2DIM + c);
    float4 bb = *(const float4*)(b2 + c);
    float4 o;
    o.x = acc.x + h.x * self + bb.x;
    o.y = acc.y + h.y * self + bb.y;
    o.z = acc.z + h.z * self + bb.z;
    o.w = acc.w + h.w * self + bb.w;
    *(float4*)(g_h2 + (size_t)node * H2DIM + c) = o;
}

// ---------------- layer-3 CSR gather + log_softmax ----------------
__global__ void gather3(float* __restrict__ out, const float* __restrict__ b3) {
    int node = blockIdx.x * (blockDim.x >> 5) + (threadIdx.x >> 5);
    if (node >= NN) return;
    int lane = threadIdx.x & 31;
    int half = lane >> 4;
    int l16 = lane & 15;
    int beg = g_off[node];
    int end = beg + g_deg[2 * NN + node];

    float acc = 0.f;
    for (int idx = beg + half; idx < end; idx += 2) {
        int sp = g_csrc[idx];
        float ca = g_coefA[idx];
        int s = sp & 0xFFFFF;
        acc += g_h3lin[(size_t)s * NCLS + l16] * ca;
    }
    acc += __shfl_down_sync(0xFFFFFFFFu, acc, 16);

    float dv = g_dinv[2 * NN + node];
    float self = dv * dv;
    float v = acc + g_h3lin[(size_t)node * NCLS + l16] * self + b3[l16];

    float m = v;
    #pragma unroll
    for (int o = 8; o > 0; o >>= 1) m = fmaxf(m, __shfl_xor_sync(0xFFFFFFFFu, m, o, 16));
    float s = expf(v - m);
    #pragma unroll
    for (int o = 8; o > 0; o >>= 1) s += __shfl_xor_sync(0xFFFFFFFFu, s, o, 16);
    float l = logf(s);
    if (lane < 16) out[(size_t)node * NCLS + l16] = v - m - l;
}

// ---------------- host launcher ----------------
extern "C" void kernel_launch(void* const* d_in, const int* in_sizes, int n_in,
                              void* d_out, int out_size) {
    const float* x    = (const float*)d_in[0];
    const int*   eidx = (const int*)d_in[1];
    const int    E    = in_sizes[1] / 2;
    const int*   src  = eidx;
    const int*   dst  = eidx + E;
    const int*   rev  = (const int*)d_in[2];
    const float* W_st = (const float*)d_in[3];
    const float* b_st = (const float*)d_in[4];
    const float* W_ts = (const float*)d_in[5];
    const float* b_ts = (const float*)d_in[6];
    const float* W1   = (const float*)d_in[7];
    const float* b1   = (const float*)d_in[8];
    const float* W2   = (const float*)d_in[9];
    const float* b2   = (const float*)d_in[10];
    const float* W3   = (const float*)d_in[11];
    const float* b3   = (const float*)d_in[12];
    float* out = (float*)d_out;

    float *h2, *h3lin;
    __half *hlin16, *h2lin16;
    __nv_bfloat16 *xhi, *xlo, *h1hi, *h1lo, *B1hi, *B1lo, *B2hi, *B2lo;
    cudaGetSymbolAddress((void**)&hlin16,  g_hlin16);
    cudaGetSymbolAddress((void**)&h2lin16, g_h2lin16);
    cudaGetSymbolAddress((void**)&h2,      g_h2);
    cudaGetSymbolAddress((void**)&h3lin,   g_h3lin);
    cudaGetSymbolAddress((void**)&xhi,     g_xhi);
    cudaGetSymbolAddress((void**)&xlo,     g_xlo);
    cudaGetSymbolAddress((void**)&h1hi,    g_h1hi);
    cudaGetSymbolAddress((void**)&h1lo,    g_h1lo);
    cudaGetSymbolAddress((void**)&B1hi,    g_B1hi);
    cudaGetSymbolAddress((void**)&B1lo,    g_B1lo);
    cudaGetSymbolAddress((void**)&B2hi,    g_B2hi);
    cudaGetSymbolAddress((void**)&B2lo,    g_B2lo);

    cudaFuncSetAttribute(mma_gemm, cudaFuncAttributeMaxDynamicSharedMemorySize, 160000);

    const int nb = (NN + 255) / 256;

    // ---- CSR + normalization build ----
    zero_deg<<<(3 * NN + 255) / 256, 256>>>();
    deg_kernel<<<(E + 255) / 256, 256>>>(dst, rev, E);
    scan_block<<<nb, 256>>>();
    scan_partials<<<1, 512>>>(nb);
    scan_add_dinv<<<(3 * NN + 255) / 256, 256>>>();
    fill_csr<<<(E + 255) / 256, 256>>>(src, dst, rev, E);

    // ---- operand prep ----
    split_x<<<((NN * F_IN / 4) + 255) / 256, 256>>>(x);
    wprep1<<<(3 * 64 * F_IN + 255) / 256, 256>>>(W_st, W_ts, W1);
    wprep2<<<(2 * 64 * H1DIM + 255) / 256, 256>>>(W2);

    const int gblocks = (NN + 127) / 128;   // 782

    // ---- layer 1: [100k,128] @ [128,192], fp16 out ----
    {
        int smem = 384 * (F_IN + 8) * 2;    // 104448
        mma_gemm<<<dim3(3, gblocks), 256, smem>>>(xhi, xlo, B1hi, B1lo, hlin16, NN, F_IN, 3);
    }
    gather1<<<(NN * 32 + 255) / 256, 256>>>(b_st, b_ts, b1);

    // ---- layer 2: [100k,192] @ [192,128], fp16 out ----
    {
        int smem = 384 * (H1DIM + 8) * 2;   // 153600
        mma_gemm<<<dim3(2, gblocks), 256, smem>>>(h1hi, h1lo, B2hi, B2lo, h2lin16, NN, H1DIM, 2);
    }
    gather2<<<(NN * 32 + 255) / 256, 256>>>(b2);

    // ---- layer 3 (fp32 SGEMM, tiny) ----
    dim3 g3(1, gblocks);
    sgemm_kernel<<<g3, 256>>>(h2, W3, h3lin, NN, NCLS, H2DIM, NCLS);
    gather3<<<(NN * 32 + 255) / 256, 256>>>(out, b3);
}

// round 6
// speedup vs baseline: 1.8313x; 1.0498x over previous
#include <cuda_runtime.h>
#include <cuda_bf16.h>
#include <cuda_fp16.h>
#include <math.h>
#include <cstdint>

#define NN    100000
#define F_IN  128
#define H1DIM 192     // 64 st + 64 ts + 64 all
#define H2DIM 128
#define NCLS  16
#define EMAX  1600000

// ---------------- device scratch (static, no allocation) ----------------
__device__ __half g_hlin16 [(size_t)NN * H1DIM];  // x @ [W_st|W_ts|W1]  (fp16)
__device__ __nv_bfloat16 g_h1b[(size_t)NN * H1DIM];  // h1 (bf16, GEMM2 A input)
__device__ __half g_h2lin16[(size_t)NN * H2DIM]; // h1 @ W2 (fp16)
__device__ float  g_h2   [(size_t)NN * H2DIM];   // gcn layer2 (fp32, sgemm3 input)
__device__ float  g_h3lin[(size_t)NN * NCLS];    // h2 @ W3
__device__ __nv_bfloat16 g_xhi[(size_t)NN * F_IN];
__device__ __nv_bfloat16 g_xlo[(size_t)NN * F_IN];
__device__ __nv_bfloat16 g_B1hi[3 * 64 * F_IN];   // W1cat^T tiles [t][n][k]
__device__ __nv_bfloat16 g_B1lo[3 * 64 * F_IN];
__device__ __nv_bfloat16 g_B2hi[2 * 64 * H1DIM];  // W2^T tiles
__device__ __nv_bfloat16 g_B2lo[2 * 64 * H1DIM];
__device__ float g_dinv [3 * NN];
__device__ int   g_deg  [3 * NN];
__device__ int   g_off  [NN];
__device__ int   g_cur  [NN];
__device__ int   g_bsum [512];
__device__ int4  g_epack[EMAX];   // {src|rev<<20, coefA bits, coefM bits, 0}, CSR order

__device__ __forceinline__ uint32_t smem_to_u32(const void* p) {
    uint32_t a;
    asm("{ .reg .u64 t; cvta.to.shared.u64 t, %1; cvt.u32.u64 %0, t; }" : "=r"(a) : "l"(p));
    return a;
}

// ---------------- small vector helpers ----------------
__device__ __forceinline__ void split4(float4 v, __nv_bfloat16* hi, __nv_bfloat16* lo, size_t idx) {
    __nv_bfloat16 hx = __float2bfloat16(v.x), hy = __float2bfloat16(v.y);
    __nv_bfloat16 hz = __float2bfloat16(v.z), hw = __float2bfloat16(v.w);
    __nv_bfloat16 lx = __float2bfloat16(v.x - __bfloat162float(hx));
    __nv_bfloat16 ly = __float2bfloat16(v.y - __bfloat162float(hy));
    __nv_bfloat16 lz = __float2bfloat16(v.z - __bfloat162float(hz));
    __nv_bfloat16 lw = __float2bfloat16(v.w - __bfloat162float(hw));
    ((__nv_bfloat162*)(hi + idx))[0] = __nv_bfloat162(hx, hy);
    ((__nv_bfloat162*)(hi + idx))[1] = __nv_bfloat162(hz, hw);
    ((__nv_bfloat162*)(lo + idx))[0] = __nv_bfloat162(lx, ly);
    ((__nv_bfloat162*)(lo + idx))[1] = __nv_bfloat162(lz, lw);
}
__device__ __forceinline__ void ldh8(float* f, const __half* p) {
    uint4 u = *(const uint4*)p;
    const __half2* h = (const __half2*)&u;
    float2 a0 = __half22float2(h[0]), a1 = __half22float2(h[1]);
    float2 a2 = __half22float2(h[2]), a3 = __half22float2(h[3]);
    f[0] = a0.x; f[1] = a0.y; f[2] = a1.x; f[3] = a1.y;
    f[4] = a2.x; f[5] = a2.y; f[6] = a3.x; f[7] = a3.y;
}
__device__ __forceinline__ void stb8(__nv_bfloat16* p, const float* f) {
    uint4 u;
    __nv_bfloat162* h = (__nv_bfloat162*)&u;
    h[0] = __nv_bfloat162(__float2bfloat16(f[0]), __float2bfloat16(f[1]));
    h[1] = __nv_bfloat162(__float2bfloat16(f[2]), __float2bfloat16(f[3]));
    h[2] = __nv_bfloat162(__float2bfloat16(f[4]), __float2bfloat16(f[5]));
    h[3] = __nv_bfloat162(__float2bfloat16(f[6]), __float2bfloat16(f[7]));
    *(uint4*)p = u;
}

// ---------------- CSR build ----------------
__global__ void zero_deg() {
    int i = blockIdx.x * blockDim.x + threadIdx.x;
    if (i < 3 * NN) g_deg[i] = 0;
}
__global__ void deg_kernel(const int* __restrict__ dst, const int* __restrict__ rev, int E) {
    int e = blockIdx.x * blockDim.x + threadIdx.x;
    if (e >= E) return;
    int d = dst[e];
    atomicAdd(&g_deg[2 * NN + d], 1);
    atomicAdd(&g_deg[(rev[e] ? NN : 0) + d], 1);
}
__global__ void scan_block() {
    __shared__ int sh[256];
    int tid = threadIdx.x;
    int i = blockIdx.x * 256 + tid;
    int v = (i < NN) ? g_deg[2 * NN + i] : 0;
    sh[tid] = v;
    __syncthreads();
    #pragma unroll
    for (int off = 1; off < 256; off <<= 1) {
        int t = (tid >= off) ? sh[tid - off] : 0;
        __syncthreads();
        sh[tid] += t;
        __syncthreads();
    }
    if (i < NN) g_off[i] = sh[tid] - v;
    if (tid == 255) g_bsum[blockIdx.x] = sh[255];
}
__global__ void scan_partials(int nb) {
    __shared__ int sh[512];
    int tid = threadIdx.x;
    int v = (tid < nb) ? g_bsum[tid] : 0;
    sh[tid] = v;
    __syncthreads();
    #pragma unroll
    for (int off = 1; off < 512; off <<= 1) {
        int t = (tid >= off) ? sh[tid - off] : 0;
        __syncthreads();
        sh[tid] += t;
        __syncthreads();
    }
    if (tid < nb) g_bsum[tid] = sh[tid] - v;
}
__global__ void scan_add_dinv() {
    int i = blockIdx.x * blockDim.x + threadIdx.x;
    if (i >= 3 * NN) return;
    g_dinv[i] = rsqrtf((float)g_deg[i] + 1.0f);
    if (i < NN) {
        int o = g_off[i] + g_bsum[i >> 8];
        g_off[i] = o;
        g_cur[i] = o;
    }
}
__global__ void fill_csr(const int* __restrict__ src, const int* __restrict__ dst,
                         const int* __restrict__ rev, int E) {
    int e = blockIdx.x * blockDim.x + threadIdx.x;
    if (e >= E) return;
    int s = src[e], d = dst[e], r = rev[e];
    int pos = atomicAdd(&g_cur[d], 1);
    float cA = g_dinv[2 * NN + s] * g_dinv[2 * NN + d];
    const float* dv = g_dinv + (r ? NN : 0);
    float cM = dv[s] * dv[d];
    g_epack[pos] = make_int4(s | (r << 20), __float_as_int(cA), __float_as_int(cM), 0);
}

// ---------------- split x into bf16 hi/lo ----------------
__global__ void split_x(const float* __restrict__ x) {
    long i = (long)blockIdx.x * blockDim.x + threadIdx.x;
    if (i >= (long)NN * F_IN / 4) return;
    float4 v = ((const float4*)x)[i];
    split4(v, g_xhi, g_xlo, (size_t)i * 4);
}

// ---------------- weight prep: transpose + split ----------------
__global__ void wprep1(const float* __restrict__ Wst, const float* __restrict__ Wts,
                       const float* __restrict__ W1f) {
    int i = blockIdx.x * blockDim.x + threadIdx.x;
    if (i >= 3 * 64 * F_IN) return;
    int t = i / (64 * F_IN);
    int n = (i / F_IN) % 64;
    int k = i % F_IN;
    const float* W = (t == 0) ? Wst : (t == 1) ? Wts : W1f;
    float v = W[k * 64 + n];
    __nv_bfloat16 h = __float2bfloat16(v);
    g_B1hi[i] = h;
    g_B1lo[i] = __float2bfloat16(v - __bfloat162float(h));
}
__global__ void wprep2(const float* __restrict__ W2) {
    int i = blockIdx.x * blockDim.x + threadIdx.x;
    if (i >= 2 * 64 * H1DIM) return;
    int t = i / (64 * H1DIM);
    int n = (i / H1DIM) % 64;
    int k = i % H1DIM;
    float v = W2[k * H2DIM + t * 64 + n];
    __nv_bfloat16 h = __float2bfloat16(v);
    g_B2hi[i] = h;
    g_B2lo[i] = __float2bfloat16(v - __bfloat162float(h));
}

// ================= mma.sync bf16 GEMM (templated on split-A) =================
__device__ __forceinline__ void ldsm_x4(uint32_t* r, uint32_t addr) {
    asm volatile("ldmatrix.sync.aligned.m8n8.x4.shared.b16 {%0,%1,%2,%3}, [%4];"
                 : "=r"(r[0]), "=r"(r[1]), "=r"(r[2]), "=r"(r[3]) : "r"(addr));
}
__device__ __forceinline__ void mma_bf16(float* c, const uint32_t* a, const uint32_t* b) {
    asm volatile("mma.sync.aligned.m16n8k16.row.col.f32.bf16.bf16.f32 "
                 "{%0,%1,%2,%3}, {%4,%5,%6,%7}, {%8,%9}, {%0,%1,%2,%3};"
                 : "+f"(c[0]), "+f"(c[1]), "+f"(c[2]), "+f"(c[3])
                 : "r"(a[0]), "r"(a[1]), "r"(a[2]), "r"(a[3]), "r"(b[0]), "r"(b[1]));
}

template <bool SPLITA>
__global__ void __launch_bounds__(256, 1)
mma_gemm(const __nv_bfloat16* __restrict__ Ahi, const __nv_bfloat16* __restrict__ Alo,
         const __nv_bfloat16* __restrict__ Bhi, const __nv_bfloat16* __restrict__ Blo,
         __half* __restrict__ C, int M, int K, int NT) {
    extern __shared__ char smem[];
    const int lda = K + 8;
    const uint32_t sAhi = 0;
    const uint32_t sAlo = SPLITA ? sAhi + 128 * lda * 2 : sAhi;
    const uint32_t sBhi = sAlo + 128 * lda * 2;
    const uint32_t sBlo = sBhi + 64 * lda * 2;
    const uint32_t sbase = smem_to_u32(smem);

    const int tid = threadIdx.x;
    const int mb = blockIdx.y * 128;
    const int bx = blockIdx.x;
    const int kc8 = K / 8;

    for (int idx = tid; idx < 128 * kc8; idx += 256) {
        int ml = idx / kc8;
        int k0 = (idx % kc8) * 8;
        int row = mb + ml;
        uint4 vh = make_uint4(0, 0, 0, 0), vl = make_uint4(0, 0, 0, 0);
        if (row < M) {
            vh = *(const uint4*)(Ahi + (size_t)row * K + k0);
            if (SPLITA) vl = *(const uint4*)(Alo + (size_t)row * K + k0);
        }
        uint32_t off = (uint32_t)(ml * lda + k0) * 2;
        *(uint4*)(smem + sAhi + off) = vh;
        if (SPLITA) *(uint4*)(smem + sAlo + off) = vl;
    }
    const __nv_bfloat16* Bht = Bhi + (size_t)bx * 64 * K;
    const __nv_bfloat16* Blt = Blo + (size_t)bx * 64 * K;
    for (int idx = tid; idx < 64 * kc8; idx += 256) {
        int nl = idx / kc8;
        int k0 = (idx % kc8) * 8;
        uint4 vh = *(const uint4*)(Bht + (size_t)nl * K + k0);
        uint4 vl = *(const uint4*)(Blt + (size_t)nl * K + k0);
        uint32_t off = (uint32_t)(nl * lda + k0) * 2;
        *(uint4*)(smem + sBhi + off) = vh;
        *(uint4*)(smem + sBlo + off) = vl;
    }
    __syncthreads();

    const int warp = tid >> 5;
    const int lane = tid & 31;
    const int wm = (warp & 3) * 32;
    const int wn = (warp >> 2) * 32;

    float c[2][4][4];
    #pragma unroll
    for (int mi = 0; mi < 2; mi++)
        #pragma unroll
        for (int ni = 0; ni < 4; ni++)
            #pragma unroll
            for (int j = 0; j < 4; j++) c[mi][ni][j] = 0.f;

    const int a_m = wm + (lane & 15);
    const int a_k = (lane >> 4) * 8;
    const int b_n = wn + ((lane >> 4) & 1) * 8 + (lane & 7);
    const int b_k = ((lane >> 3) & 1) * 8;

    for (int k0 = 0; k0 < K; k0 += 16) {
        uint32_t ah[2][4], al[2][4];
        #pragma unroll
        for (int mi = 0; mi < 2; mi++) {
            uint32_t off = (uint32_t)((a_m + mi * 16) * lda + k0 + a_k) * 2;
            ldsm_x4(ah[mi], sbase + sAhi + off);
            if (SPLITA) ldsm_x4(al[mi], sbase + sAlo + off);
        }
        uint32_t bh[4][2], bl[4][2];
        #pragma unroll
        for (int ni2 = 0; ni2 < 2; ni2++) {
            uint32_t tmp[4];
            uint32_t off = (uint32_t)((b_n + ni2 * 16) * lda + k0 + b_k) * 2;
            ldsm_x4(tmp, sbase + sBhi + off);
            bh[ni2 * 2 + 0][0] = tmp[0]; bh[ni2 * 2 + 0][1] = tmp[1];
            bh[ni2 * 2 + 1][0] = tmp[2]; bh[ni2 * 2 + 1][1] = tmp[3];
            ldsm_x4(tmp, sbase + sBlo + off);
            bl[ni2 * 2 + 0][0] = tmp[0]; bl[ni2 * 2 + 0][1] = tmp[1];
            bl[ni2 * 2 + 1][0] = tmp[2]; bl[ni2 * 2 + 1][1] = tmp[3];
        }
        #pragma unroll
        for (int mi = 0; mi < 2; mi++)
            #pragma unroll
            for (int ni = 0; ni < 4; ni++) {
                mma_bf16(c[mi][ni], ah[mi], bh[ni]);
                mma_bf16(c[mi][ni], ah[mi], bl[ni]);
                if (SPLITA) mma_bf16(c[mi][ni], al[mi], bh[ni]);
            }
    }

    const int ldc = NT * 64;
    const int r0 = lane >> 2;
    const int c0 = (lane & 3) * 2;
    #pragma unroll
    for (int mi = 0; mi < 2; mi++) {
        #pragma unroll
        for (int ni = 0; ni < 4; ni++) {
            int gcol = bx * 64 + wn + ni * 8 + c0;
            int grow0 = mb + wm + mi * 16 + r0;
            int grow1 = grow0 + 8;
            if (grow0 < M) {
                __half2 v = __floats2half2_rn(c[mi][ni][0], c[mi][ni][1]);
                *(__half2*)(C + (size_t)grow0 * ldc + gcol) = v;
            }
            if (grow1 < M) {
                __half2 v = __floats2half2_rn(c[mi][ni][2], c[mi][ni][3]);
                *(__half2*)(C + (size_t)grow1 * ldc + gcol) = v;
            }
        }
    }
}

// ---------------- fp32 SGEMM (layer 3 only) ----------------
__global__ void __launch_bounds__(256)
sgemm_kernel(const float* __restrict__ A, const float* __restrict__ B,
             float* __restrict__ C, int M, int Nc, int K, int ldc) {
    const int BM = 128, BK = 16;
    __shared__ float As[BK][BM];
    __shared__ float Bs[BK][64];
    int tid = threadIdx.x;
    int rowBlock = blockIdx.y * BM;
    int colBlock = blockIdx.x * 64;
    int tr = tid >> 4, tc = tid & 15;
    float acc[8][4];
    #pragma unroll
    for (int i = 0; i < 8; i++)
        #pragma unroll
        for (int j = 0; j < 4; j++) acc[i][j] = 0.f;
    int arow = tid >> 2, acol = (tid & 3) << 2;
    int brow = tid >> 4, bcol = (tid & 15) << 2;
    for (int k0 = 0; k0 < K; k0 += BK) {
        #pragma unroll
        for (int h = 0; h < 2; h++) {
            int r = arow + h * 64;
            int grow = rowBlock + r;
            float4 va = make_float4(0.f, 0.f, 0.f, 0.f);
            if (grow < M) va = *(const float4*)(A + (size_t)grow * K + k0 + acol);
            As[acol + 0][r] = va.x; As[acol + 1][r] = va.y;
            As[acol + 2][r] = va.z; As[acol + 3][r] = va.w;
        }
        {
            int gcol = colBlock + bcol;
            float t0 = (gcol + 0 < Nc) ? B[(size_t)(k0 + brow) * Nc + gcol + 0] : 0.f;
            float t1 = (gcol + 1 < Nc) ? B[(size_t)(k0 + brow) * Nc + gcol + 1] : 0.f;
            float t2 = (gcol + 2 < Nc) ? B[(size_t)(k0 + brow) * Nc + gcol + 2] : 0.f;
            float t3 = (gcol + 3 < Nc) ? B[(size_t)(k0 + brow) * Nc + gcol + 3] : 0.f;
            Bs[brow][bcol + 0] = t0; Bs[brow][bcol + 1] = t1;
            Bs[brow][bcol + 2] = t2; Bs[brow][bcol + 3] = t3;
        }
        __syncthreads();
        #pragma unroll
        for (int kk = 0; kk < BK; kk++) {
            float a[8], b[4];
            #pragma unroll
            for (int i = 0; i < 8; i++) a[i] = As[kk][tr * 8 + i];
            #pragma unroll
            for (int j = 0; j < 4; j++) b[j] = Bs[kk][tc * 4 + j];
            #pragma unroll
            for (int i = 0; i < 8; i++)
                #pragma unroll
                for (int j = 0; j < 4; j++) acc[i][j] += a[i] * b[j];
        }
        __syncthreads();
    }
    #pragma unroll
    for (int i = 0; i < 8; i++) {
        int grow = rowBlock + tr * 8 + i;
        if (grow >= M) continue;
        #pragma unroll
        for (int j = 0; j < 4; j++) {
            int gcol = colBlock + tc * 4 + j;
            if (gcol < Nc) C[(size_t)grow * ldc + gcol] = acc[i][j];
        }
    }
}

// ---------------- layer-1 CSR gather: warp/node, 2 edges per iteration ----------------
// lane roles: q = lane>>3 (0..3); halves (q<2 / q>=2) take edges j / j+1.
// within a half: q even -> masked block (cols l8*8 of st or ts, by edge's rev)
//                q odd  -> all block   (cols 128 + l8*8)
__global__ void gather1(const float* __restrict__ b_st, const float* __restrict__ b_ts,
                        const float* __restrict__ b1) {
    int node = blockIdx.x * (blockDim.x >> 5) + (threadIdx.x >> 5);
    if (node >= NN) return;
    int lane = threadIdx.x & 31;
    int l8 = lane & 7;
    bool maskedRole = ((lane >> 3) & 1) == 0;
    int half = lane >> 4;
    int beg = g_off[node];
    int deg = g_epack ? 0 : 0;   // placate compiler ordering
    deg = g_deg[2 * NN + node];
    int end = beg + deg;

    float accST[8], accTS[8], accA[8];
    #pragma unroll
    for (int i = 0; i < 8; i++) { accST[i] = 0.f; accTS[i] = 0.f; accA[i] = 0.f; }

    #pragma unroll 2
    for (int j = beg; j < end; j += 2) {
        int e = j + half;
        if (e < end) {
            int4 mt = g_epack[e];
            int s = mt.x & 0xFFFFF;
            int r = mt.x >> 20;
            if (maskedRole) {
                float cm = __int_as_float(mt.z);
                float f[8];
                ldh8(f, g_hlin16 + (size_t)s * H1DIM + (r ? 64 : 0) + l8 * 8);
                float* acc = r ? accTS : accST;
                #pragma unroll
                for (int i = 0; i < 8; i++) acc[i] += f[i] * cm;
            } else {
                float ca = __int_as_float(mt.y);
                float f[8];
                ldh8(f, g_hlin16 + (size_t)s * H1DIM + 128 + l8 * 8);
                #pragma unroll
                for (int i = 0; i < 8; i++) accA[i] += f[i] * ca;
            }
        }
    }
    // merge the two halves (each column owned by lane and lane^16)
    #pragma unroll
    for (int i = 0; i < 8; i++) {
        accST[i] += __shfl_xor_sync(0xFFFFFFFFu, accST[i], 16);
        accTS[i] += __shfl_xor_sync(0xFFFFFFFFu, accTS[i], 16);
        accA[i]  += __shfl_xor_sync(0xFFFFFFFFu, accA[i], 16);
    }

    if (lane >= 16) return;
    const __half* hrow = g_hlin16 + (size_t)node * H1DIM;
    __nv_bfloat16* orow = g_h1b + (size_t)node * H1DIM;
    int c = l8 * 8;
    if (maskedRole) {
        // st block
        float dv = g_dinv[node];
        float self = dv * dv;
        float h[8], o[8];
        ldh8(h, hrow + c);
        #pragma unroll
        for (int i = 0; i < 8; i++) o[i] = fmaxf(accST[i] + h[i] * self + b_st[c + i], 0.f);
        stb8(orow + c, o);
        // ts block
        dv = g_dinv[NN + node];
        self = dv * dv;
        ldh8(h, hrow + 64 + c);
        #pragma unroll
        for (int i = 0; i < 8; i++) o[i] = fmaxf(accTS[i] + h[i] * self + b_ts[c + i], 0.f);
        stb8(orow + 64 + c, o);
    } else {
        float dv = g_dinv[2 * NN + node];
        float self = dv * dv;
        float h[8], o[8];
        ldh8(h, hrow + 128 + c);
        #pragma unroll
        for (int i = 0; i < 8; i++) o[i] = fmaxf(accA[i] + h[i] * self + b1[c + i], 0.f);
        stb8(orow + 128 + c, o);
    }
}

// ---------------- layer-2 CSR gather: warp/node, 2 edges per iteration ----------------
__global__ void gather2(const float* __restrict__ b2) {
    int node = blockIdx.x * (blockDim.x >> 5) + (threadIdx.x >> 5);
    if (node >= NN) return;
    int lane = threadIdx.x & 31;
    int l = lane & 15;                  // column group: cols l*8..+7
    int half = lane >> 4;
    int beg = g_off[node];
    int end = beg + g_deg[2 * NN + node];

    float acc[8];
    #pragma unroll
    for (int i = 0; i < 8; i++) acc[i] = 0.f;

    #pragma unroll 2
    for (int j = beg; j < end; j += 2) {
        int e = j + half;
        if (e < end) {
            int4 mt = g_epack[e];
            int s = mt.x & 0xFFFFF;
            float ca = __int_as_float(mt.y);
            float f[8];
            ldh8(f, g_h2lin16 + (size_t)s * H2DIM + l * 8);
            #pragma unroll
            for (int i = 0; i < 8; i++) acc[i] += f[i] * ca;
        }
    }
    #pragma unroll
    for (int i = 0; i < 8; i++) acc[i] += __shfl_xor_sync(0xFFFFFFFFu, acc[i], 16);

    if (lane >= 16) return;
    float dv = g_dinv[2 * NN + node];
    float self = dv * dv;
    int c = l * 8;
    float h[8];
    ldh8(h, g_h2lin16 + (size_t)node * H2DIM + c);
    float* orow = g_h2 + (size_t)node * H2DIM + c;
    float4 o0, o1;
    o0.x = acc[0] + h[0] * self + b2[c + 0];
    o0.y = acc[1] + h[1] * self + b2[c + 1];
    o0.z = acc[2] + h[2] * self + b2[c + 2];
    o0.w = acc[3] + h[3] * self + b2[c + 3];
    o1.x = acc[4] + h[4] * self + b2[c + 4];
    o1.y = acc[5] + h[5] * self + b2[c + 5];
    o1.z = acc[6] + h[6] * self + b2[c + 6];
    o1.w = acc[7] + h[7] * self + b2[c + 7];
    *(float4*)orow = o0;
    *(float4*)(orow + 4) = o1;
}

// ---------------- layer-3 CSR gather + log_softmax ----------------
__global__ void gather3(float* __restrict__ out, const float* __restrict__ b3) {
    int node = blockIdx.x * (blockDim.x >> 5) + (threadIdx.x >> 5);
    if (node >= NN) return;
    int lane = threadIdx.x & 31;
    int half = lane >> 4;
    int l16 = lane & 15;
    int beg = g_off[node];
    int end = beg + g_deg[2 * NN + node];

    float acc = 0.f;
    #pragma unroll 2
    for (int idx = beg + half; idx < end; idx += 2) {
        int4 mt = g_epack[idx];
        int s = mt.x & 0xFFFFF;
        float ca = __int_as_float(mt.y);
        acc += g_h3lin[(size_t)s * NCLS + l16] * ca;
    }
    acc += __shfl_down_sync(0xFFFFFFFFu, acc, 16);

    float dv = g_dinv[2 * NN + node];
    float self = dv * dv;
    float v = acc + g_h3lin[(size_t)node * NCLS + l16] * self + b3[l16];

    float m = v;
    #pragma unroll
    for (int o = 8; o > 0; o >>= 1) m = fmaxf(m, __shfl_xor_sync(0xFFFFFFFFu, m, o, 16));
    float s = expf(v - m);
    #pragma unroll
    for (int o = 8; o > 0; o >>= 1) s += __shfl_xor_sync(0xFFFFFFFFu, s, o, 16);
    float l = logf(s);
    if (lane < 16) out[(size_t)node * NCLS + l16] = v - m - l;
}

// ---------------- host launcher ----------------
extern "C" void kernel_launch(void* const* d_in, const int* in_sizes, int n_in,
                              void* d_out, int out_size) {
    const float* x    = (const float*)d_in[0];
    const int*   eidx = (const int*)d_in[1];
    const int    E    = in_sizes[1] / 2;
    const int*   src  = eidx;
    const int*   dst  = eidx + E;
    const int*   rev  = (const int*)d_in[2];
    const float* W_st = (const float*)d_in[3];
    const float* b_st = (const float*)d_in[4];
    const float* W_ts = (const float*)d_in[5];
    const float* b_ts = (const float*)d_in[6];
    const float* W1   = (const float*)d_in[7];
    const float* b1   = (const float*)d_in[8];
    const float* W2   = (const float*)d_in[9];
    const float* b2   = (const float*)d_in[10];
    const float* W3   = (const float*)d_in[11];
    const float* b3   = (const float*)d_in[12];
    float* out = (float*)d_out;

    float *h2, *h3lin;
    __half *hlin16, *h2lin16;
    __nv_bfloat16 *xhi, *xlo, *h1b, *B1hi, *B1lo, *B2hi, *B2lo;
    cudaGetSymbolAddress((void**)&hlin16,  g_hlin16);
    cudaGetSymbolAddress((void**)&h2lin16, g_h2lin16);
    cudaGetSymbolAddress((void**)&h2,      g_h2);
    cudaGetSymbolAddress((void**)&h3lin,   g_h3lin);
    cudaGetSymbolAddress((void**)&xhi,     g_xhi);
    cudaGetSymbolAddress((void**)&xlo,     g_xlo);
    cudaGetSymbolAddress((void**)&h1b,     g_h1b);
    cudaGetSymbolAddress((void**)&B1hi,    g_B1hi);
    cudaGetSymbolAddress((void**)&B1lo,    g_B1lo);
    cudaGetSymbolAddress((void**)&B2hi,    g_B2hi);
    cudaGetSymbolAddress((void**)&B2lo,    g_B2lo);

    cudaFuncSetAttribute(mma_gemm<true>,  cudaFuncAttributeMaxDynamicSharedMemorySize, 110000);
    cudaFuncSetAttribute(mma_gemm<false>, cudaFuncAttributeMaxDynamicSharedMemorySize, 110000);

    const int nb = (NN + 255) / 256;

    // ---- CSR + normalization build ----
    zero_deg<<<(3 * NN + 255) / 256, 256>>>();
    deg_kernel<<<(E + 255) / 256, 256>>>(dst, rev, E);
    scan_block<<<nb, 256>>>();
    scan_partials<<<1, 512>>>(nb);
    scan_add_dinv<<<(3 * NN + 255) / 256, 256>>>();
    fill_csr<<<(E + 255) / 256, 256>>>(src, dst, rev, E);

    // ---- operand prep ----
    split_x<<<((NN * F_IN / 4) + 255) / 256, 256>>>(x);
    wprep1<<<(3 * 64 * F_IN + 255) / 256, 256>>>(W_st, W_ts, W1);
    wprep2<<<(2 * 64 * H1DIM + 255) / 256, 256>>>(W2);

    const int gblocks = (NN + 127) / 128;   // 782

    // ---- layer 1: split-A 3-pass, fp16 out ----
    {
        int smem = 384 * (F_IN + 8) * 2;    // 104448
        mma_gemm<true><<<dim3(3, gblocks), 256, smem>>>(xhi, xlo, B1hi, B1lo, hlin16, NN, F_IN, 3);
    }
    gather1<<<(NN * 32 + 255) / 256, 256>>>(b_st, b_ts, b1);

    // ---- layer 2: single-A 2-pass, fp16 out ----
    {
        int smem = 256 * (H1DIM + 8) * 2;   // 102400
        mma_gemm<false><<<dim3(2, gblocks), 256, smem>>>(h1b, nullptr, B2hi, B2lo, h2lin16, NN, H1DIM, 2);
    }
    gather2<<<(NN * 32 + 255) / 256, 256>>>(b2);

    // ---- layer 3 (fp32 SGEMM, tiny) ----
    dim3 g3(1, gblocks);
    sgemm_kernel<<<g3, 256>>>(h2, W3, h3lin, NN, NCLS, H2DIM, NCLS);
    gather3<<<(NN * 32 + 255) / 256, 256>>>(out, b3);
}

// round 7
// speedup vs baseline: 1.8956x; 1.0351x over previous
#include <cuda_runtime.h>
#include <cuda_bf16.h>
#include <cuda_fp16.h>
#include <math.h>
#include <cstdint>

#define NN    100000
#define F_IN  128
#define H1DIM 192     // 64 st + 64 ts + 64 all
#define H2DIM 128
#define NCLS  16
#define EMAX  1600000

// ---------------- device scratch (static, no allocation) ----------------
__device__ __half g_hlin16 [(size_t)NN * H1DIM];  // x @ [W_st|W_ts|W1]  (fp16)
__device__ __nv_bfloat16 g_h1b[(size_t)NN * H1DIM];  // h1 (bf16, GEMM2 A input)
__device__ __half g_h2lin16[(size_t)NN * H2DIM]; // h1 @ W2 (fp16)
__device__ __half g_h2_16 [(size_t)NN * H2DIM];  // gcn layer2 (fp16, sgemm3 input)
__device__ float  g_h3lin[(size_t)NN * NCLS];    // h2 @ W3
__device__ __nv_bfloat16 g_B1hi[3 * 64 * F_IN];   // W1cat^T tiles [t][n][k]
__device__ __nv_bfloat16 g_B1lo[3 * 64 * F_IN];
__device__ __nv_bfloat16 g_B2hi[2 * 64 * H1DIM];  // W2^T tiles
__device__ __nv_bfloat16 g_B2lo[2 * 64 * H1DIM];
__device__ float g_dinv [3 * NN];
__device__ int   g_deg  [3 * NN];
__device__ int   g_off  [NN];
__device__ int   g_cur  [NN];
__device__ int   g_bsum [512];
__device__ int4  g_epack[EMAX];   // {src|rev<<20, coefA bits, coefM bits, 0}, CSR order

__device__ __forceinline__ uint32_t smem_to_u32(const void* p) {
    uint32_t a;
    asm("{ .reg .u64 t; cvta.to.shared.u64 t, %1; cvt.u32.u64 %0, t; }" : "=r"(a) : "l"(p));
    return a;
}

// ---------------- small vector helpers ----------------
__device__ __forceinline__ void split8_store(const float* f, char* hi, char* lo) {
    uint4 uh, ul;
    __nv_bfloat162* hh = (__nv_bfloat162*)&uh;
    __nv_bfloat162* ll = (__nv_bfloat162*)&ul;
    #pragma unroll
    for (int i = 0; i < 4; i++) {
        float a = f[2 * i], b = f[2 * i + 1];
        __nv_bfloat16 ha = __float2bfloat16(a), hb = __float2bfloat16(b);
        hh[i] = __nv_bfloat162(ha, hb);
        ll[i] = __nv_bfloat162(__float2bfloat16(a - __bfloat162float(ha)),
                               __float2bfloat16(b - __bfloat162float(hb)));
    }
    *(uint4*)hi = uh;
    *(uint4*)lo = ul;
}
__device__ __forceinline__ void ldh8(float* f, const __half* p) {
    uint4 u = *(const uint4*)p;
    const __half2* h = (const __half2*)&u;
    float2 a0 = __half22float2(h[0]), a1 = __half22float2(h[1]);
    float2 a2 = __half22float2(h[2]), a3 = __half22float2(h[3]);
    f[0] = a0.x; f[1] = a0.y; f[2] = a1.x; f[3] = a1.y;
    f[4] = a2.x; f[5] = a2.y; f[6] = a3.x; f[7] = a3.y;
}
__device__ __forceinline__ void stb8(__nv_bfloat16* p, const float* f) {
    uint4 u;
    __nv_bfloat162* h = (__nv_bfloat162*)&u;
    h[0] = __nv_bfloat162(__float2bfloat16(f[0]), __float2bfloat16(f[1]));
    h[1] = __nv_bfloat162(__float2bfloat16(f[2]), __float2bfloat16(f[3]));
    h[2] = __nv_bfloat162(__float2bfloat16(f[4]), __float2bfloat16(f[5]));
    h[3] = __nv_bfloat162(__float2bfloat16(f[6]), __float2bfloat16(f[7]));
    *(uint4*)p = u;
}
__device__ __forceinline__ void sth8(__half* p, const float* f) {
    uint4 u;
    __half2* h = (__half2*)&u;
    h[0] = __floats2half2_rn(f[0], f[1]);
    h[1] = __floats2half2_rn(f[2], f[3]);
    h[2] = __floats2half2_rn(f[4], f[5]);
    h[3] = __floats2half2_rn(f[6], f[7]);
    *(uint4*)p = u;
}

// ---------------- CSR build ----------------
__global__ void zero_deg() {
    int i = blockIdx.x * blockDim.x + threadIdx.x;
    if (i < 3 * NN) g_deg[i] = 0;
}
__global__ void deg_kernel(const int* __restrict__ dst, const int* __restrict__ rev, int E) {
    int e = blockIdx.x * blockDim.x + threadIdx.x;
    if (e >= E) return;
    int d = dst[e];
    atomicAdd(&g_deg[2 * NN + d], 1);
    atomicAdd(&g_deg[(rev[e] ? NN : 0) + d], 1);
}
__global__ void scan_block() {
    __shared__ int sh[256];
    int tid = threadIdx.x;
    int i = blockIdx.x * 256 + tid;
    int v = (i < NN) ? g_deg[2 * NN + i] : 0;
    sh[tid] = v;
    __syncthreads();
    #pragma unroll
    for (int off = 1; off < 256; off <<= 1) {
        int t = (tid >= off) ? sh[tid - off] : 0;
        __syncthreads();
        sh[tid] += t;
        __syncthreads();
    }
    if (i < NN) g_off[i] = sh[tid] - v;
    if (tid == 255) g_bsum[blockIdx.x] = sh[255];
}
__global__ void scan_partials(int nb) {
    __shared__ int sh[512];
    int tid = threadIdx.x;
    int v = (tid < nb) ? g_bsum[tid] : 0;
    sh[tid] = v;
    __syncthreads();
    #pragma unroll
    for (int off = 1; off < 512; off <<= 1) {
        int t = (tid >= off) ? sh[tid - off] : 0;
        __syncthreads();
        sh[tid] += t;
        __syncthreads();
    }
    if (tid < nb) g_bsum[tid] = sh[tid] - v;
}
__global__ void scan_add_dinv() {
    int i = blockIdx.x * blockDim.x + threadIdx.x;
    if (i >= 3 * NN) return;
    g_dinv[i] = rsqrtf((float)g_deg[i] + 1.0f);
    if (i < NN) {
        int o = g_off[i] + g_bsum[i >> 8];
        g_off[i] = o;
        g_cur[i] = o;
    }
}
__global__ void fill_csr(const int* __restrict__ src, const int* __restrict__ dst,
                         const int* __restrict__ rev, int E) {
    int e = blockIdx.x * blockDim.x + threadIdx.x;
    if (e >= E) return;
    int s = src[e], d = dst[e], r = rev[e];
    int pos = atomicAdd(&g_cur[d], 1);
    float cA = g_dinv[2 * NN + s] * g_dinv[2 * NN + d];
    const float* dv = g_dinv + (r ? NN : 0);
    float cM = dv[s] * dv[d];
    g_epack[pos] = make_int4(s | (r << 20), __float_as_int(cA), __float_as_int(cM), 0);
}

// ---------------- weight prep: transpose + split ----------------
__global__ void wprep1(const float* __restrict__ Wst, const float* __restrict__ Wts,
                       const float* __restrict__ W1f) {
    int i = blockIdx.x * blockDim.x + threadIdx.x;
    if (i >= 3 * 64 * F_IN) return;
    int t = i / (64 * F_IN);
    int n = (i / F_IN) % 64;
    int k = i % F_IN;
    const float* W = (t == 0) ? Wst : (t == 1) ? Wts : W1f;
    float v = W[k * 64 + n];
    __nv_bfloat16 h = __float2bfloat16(v);
    g_B1hi[i] = h;
    g_B1lo[i] = __float2bfloat16(v - __bfloat162float(h));
}
__global__ void wprep2(const float* __restrict__ W2) {
    int i = blockIdx.x * blockDim.x + threadIdx.x;
    if (i >= 2 * 64 * H1DIM) return;
    int t = i / (64 * H1DIM);
    int n = (i / H1DIM) % 64;
    int k = i % H1DIM;
    float v = W2[k * H2DIM + t * 64 + n];
    __nv_bfloat16 h = __float2bfloat16(v);
    g_B2hi[i] = h;
    g_B2lo[i] = __float2bfloat16(v - __bfloat162float(h));
}

// ================= mma.sync bf16 GEMM =================
// AMODE: 0 = single bf16 A (2 MMA passes), 1 = split bf16 A pair (3 passes),
//        2 = fp32 A split to hi/lo during staging (3 passes)
__device__ __forceinline__ void ldsm_x4(uint32_t* r, uint32_t addr) {
    asm volatile("ldmatrix.sync.aligned.m8n8.x4.shared.b16 {%0,%1,%2,%3}, [%4];"
                 : "=r"(r[0]), "=r"(r[1]), "=r"(r[2]), "=r"(r[3]) : "r"(addr));
}
__device__ __forceinline__ void mma_bf16(float* c, const uint32_t* a, const uint32_t* b) {
    asm volatile("mma.sync.aligned.m16n8k16.row.col.f32.bf16.bf16.f32 "
                 "{%0,%1,%2,%3}, {%4,%5,%6,%7}, {%8,%9}, {%0,%1,%2,%3};"
                 : "+f"(c[0]), "+f"(c[1]), "+f"(c[2]), "+f"(c[3])
                 : "r"(a[0]), "r"(a[1]), "r"(a[2]), "r"(a[3]), "r"(b[0]), "r"(b[1]));
}

template <int AMODE>
__global__ void __launch_bounds__(256, 1)
mma_gemm(const void* __restrict__ Apv, const __nv_bfloat16* __restrict__ Alo,
         const __nv_bfloat16* __restrict__ Bhi, const __nv_bfloat16* __restrict__ Blo,
         __half* __restrict__ C, int M, int K, int NT) {
    constexpr bool SPLITA = (AMODE != 0);
    extern __shared__ char smem[];
    const int lda = K + 8;
    const uint32_t sAhi = 0;
    const uint32_t sAlo = SPLITA ? sAhi + 128 * lda * 2 : sAhi;
    const uint32_t sBhi = sAlo + 128 * lda * 2;
    const uint32_t sBlo = sBhi + 64 * lda * 2;
    const uint32_t sbase = smem_to_u32(smem);

    const int tid = threadIdx.x;
    const int mb = blockIdx.y * 128;
    const int bx = blockIdx.x;
    const int kc8 = K / 8;

    // ---- stage A ----
    for (int idx = tid; idx < 128 * kc8; idx += 256) {
        int ml = idx / kc8;
        int k0 = (idx % kc8) * 8;
        int row = mb + ml;
        uint32_t off = (uint32_t)(ml * lda + k0) * 2;
        if (AMODE == 2) {
            const float* Afp = (const float*)Apv;
            float f[8] = {0.f, 0.f, 0.f, 0.f, 0.f, 0.f, 0.f, 0.f};
            if (row < M) {
                float4 a = *(const float4*)(Afp + (size_t)row * K + k0);
                float4 b = *(const float4*)(Afp + (size_t)row * K + k0 + 4);
                f[0] = a.x; f[1] = a.y; f[2] = a.z; f[3] = a.w;
                f[4] = b.x; f[5] = b.y; f[6] = b.z; f[7] = b.w;
            }
            split8_store(f, smem + sAhi + off, smem + sAlo + off);
        } else {
            const __nv_bfloat16* Ahi = (const __nv_bfloat16*)Apv;
            uint4 vh = make_uint4(0, 0, 0, 0), vl = make_uint4(0, 0, 0, 0);
            if (row < M) {
                vh = *(const uint4*)(Ahi + (size_t)row * K + k0);
                if (AMODE == 1) vl = *(const uint4*)(Alo + (size_t)row * K + k0);
            }
            *(uint4*)(smem + sAhi + off) = vh;
            if (AMODE == 1) *(uint4*)(smem + sAlo + off) = vl;
        }
    }
    // ---- stage B tile ----
    const __nv_bfloat16* Bht = Bhi + (size_t)bx * 64 * K;
    const __nv_bfloat16* Blt = Blo + (size_t)bx * 64 * K;
    for (int idx = tid; idx < 64 * kc8; idx += 256) {
        int nl = idx / kc8;
        int k0 = (idx % kc8) * 8;
        uint4 vh = *(const uint4*)(Bht + (size_t)nl * K + k0);
        uint4 vl = *(const uint4*)(Blt + (size_t)nl * K + k0);
        uint32_t off = (uint32_t)(nl * lda + k0) * 2;
        *(uint4*)(smem + sBhi + off) = vh;
        *(uint4*)(smem + sBlo + off) = vl;
    }
    __syncthreads();

    const int warp = tid >> 5;
    const int lane = tid & 31;
    const int wm = (warp & 3) * 32;
    const int wn = (warp >> 2) * 32;

    float c[2][4][4];
    #pragma unroll
    for (int mi = 0; mi < 2; mi++)
        #pragma unroll
        for (int ni = 0; ni < 4; ni++)
            #pragma unroll
            for (int j = 0; j < 4; j++) c[mi][ni][j] = 0.f;

    const int a_m = wm + (lane & 15);
    const int a_k = (lane >> 4) * 8;
    const int b_n = wn + ((lane >> 4) & 1) * 8 + (lane & 7);
    const int b_k = ((lane >> 3) & 1) * 8;

    for (int k0 = 0; k0 < K; k0 += 16) {
        uint32_t ah[2][4], al[2][4];
        #pragma unroll
        for (int mi = 0; mi < 2; mi++) {
            uint32_t off = (uint32_t)((a_m + mi * 16) * lda + k0 + a_k) * 2;
            ldsm_x4(ah[mi], sbase + sAhi + off);
            if (SPLITA) ldsm_x4(al[mi], sbase + sAlo + off);
        }
        uint32_t bh[4][2], bl[4][2];
        #pragma unroll
        for (int ni2 = 0; ni2 < 2; ni2++) {
            uint32_t tmp[4];
            uint32_t off = (uint32_t)((b_n + ni2 * 16) * lda + k0 + b_k) * 2;
            ldsm_x4(tmp, sbase + sBhi + off);
            bh[ni2 * 2 + 0][0] = tmp[0]; bh[ni2 * 2 + 0][1] = tmp[1];
            bh[ni2 * 2 + 1][0] = tmp[2]; bh[ni2 * 2 + 1][1] = tmp[3];
            ldsm_x4(tmp, sbase + sBlo + off);
            bl[ni2 * 2 + 0][0] = tmp[0]; bl[ni2 * 2 + 0][1] = tmp[1];
            bl[ni2 * 2 + 1][0] = tmp[2]; bl[ni2 * 2 + 1][1] = tmp[3];
        }
        #pragma unroll
        for (int mi = 0; mi < 2; mi++)
            #pragma unroll
            for (int ni = 0; ni < 4; ni++) {
                mma_bf16(c[mi][ni], ah[mi], bh[ni]);
                mma_bf16(c[mi][ni], ah[mi], bl[ni]);
                if (SPLITA) mma_bf16(c[mi][ni], al[mi], bh[ni]);
            }
    }

    const int ldc = NT * 64;
    const int r0 = lane >> 2;
    const int c0 = (lane & 3) * 2;
    #pragma unroll
    for (int mi = 0; mi < 2; mi++) {
        #pragma unroll
        for (int ni = 0; ni < 4; ni++) {
            int gcol = bx * 64 + wn + ni * 8 + c0;
            int grow0 = mb + wm + mi * 16 + r0;
            int grow1 = grow0 + 8;
            if (grow0 < M) {
                __half2 v = __floats2half2_rn(c[mi][ni][0], c[mi][ni][1]);
                *(__half2*)(C + (size_t)grow0 * ldc + gcol) = v;
            }
            if (grow1 < M) {
                __half2 v = __floats2half2_rn(c[mi][ni][2], c[mi][ni][3]);
                *(__half2*)(C + (size_t)grow1 * ldc + gcol) = v;
            }
        }
    }
}

// ---------------- fp16-A SGEMM (layer 3 only) ----------------
__global__ void __launch_bounds__(256)
sgemm_h(const __half* __restrict__ A, const float* __restrict__ B,
        float* __restrict__ C, int M, int Nc, int K, int ldc) {
    const int BM = 128, BK = 16;
    __shared__ float As[BK][BM];
    __shared__ float Bs[BK][64];
    int tid = threadIdx.x;
    int rowBlock = blockIdx.y * BM;
    int colBlock = blockIdx.x * 64;
    int tr = tid >> 4, tc = tid & 15;
    float acc[8][4];
    #pragma unroll
    for (int i = 0; i < 8; i++)
        #pragma unroll
        for (int j = 0; j < 4; j++) acc[i][j] = 0.f;
    int arow = tid >> 2, acol = (tid & 3) << 2;
    int brow = tid >> 4, bcol = (tid & 15) << 2;
    for (int k0 = 0; k0 < K; k0 += BK) {
        #pragma unroll
        for (int h = 0; h < 2; h++) {
            int r = arow + h * 64;
            int grow = rowBlock + r;
            float4 va = make_float4(0.f, 0.f, 0.f, 0.f);
            if (grow < M) {
                uint2 u = *(const uint2*)(A + (size_t)grow * K + k0 + acol);
                __half2 h0 = *reinterpret_cast<__half2*>(&u.x);
                __half2 h1 = *reinterpret_cast<__half2*>(&u.y);
                float2 f0 = __half22float2(h0);
                float2 f1 = __half22float2(h1);
                va = make_float4(f0.x, f0.y, f1.x, f1.y);
            }
            As[acol + 0][r] = va.x; As[acol + 1][r] = va.y;
            As[acol + 2][r] = va.z; As[acol + 3][r] = va.w;
        }
        {
            int gcol = colBlock + bcol;
            float t0 = (gcol + 0 < Nc) ? B[(size_t)(k0 + brow) * Nc + gcol + 0] : 0.f;
            float t1 = (gcol + 1 < Nc) ? B[(size_t)(k0 + brow) * Nc + gcol + 1] : 0.f;
            float t2 = (gcol + 2 < Nc) ? B[(size_t)(k0 + brow) * Nc + gcol + 2] : 0.f;
            float t3 = (gcol + 3 < Nc) ? B[(size_t)(k0 + brow) * Nc + gcol + 3] : 0.f;
            Bs[brow][bcol + 0] = t0; Bs[brow][bcol + 1] = t1;
            Bs[brow][bcol + 2] = t2; Bs[brow][bcol + 3] = t3;
        }
        __syncthreads();
        #pragma unroll
        for (int kk = 0; kk < BK; kk++) {
            float a[8], b[4];
            #pragma unroll
            for (int i = 0; i < 8; i++) a[i] = As[kk][tr * 8 + i];
            #pragma unroll
            for (int j = 0; j < 4; j++) b[j] = Bs[kk][tc * 4 + j];
            #pragma unroll
            for (int i = 0; i < 8; i++)
                #pragma unroll
                for (int j = 0; j < 4; j++) acc[i][j] += a[i] * b[j];
        }
        __syncthreads();
    }
    #pragma unroll
    for (int i = 0; i < 8; i++) {
        int grow = rowBlock + tr * 8 + i;
        if (grow >= M) continue;
        #pragma unroll
        for (int j = 0; j < 4; j++) {
            int gcol = colBlock + tc * 4 + j;
            if (gcol < Nc) C[(size_t)grow * ldc + gcol] = acc[i][j];
        }
    }
}

// ---------------- layer-1 CSR gather ----------------
__global__ void gather1(const float* __restrict__ b_st, const float* __restrict__ b_ts,
                        const float* __restrict__ b1) {
    int node = blockIdx.x * (blockDim.x >> 5) + (threadIdx.x >> 5);
    if (node >= NN) return;
    int lane = threadIdx.x & 31;
    int l8 = lane & 7;
    bool maskedRole = ((lane >> 3) & 1) == 0;
    int half = lane >> 4;
    int beg = g_off[node];
    int end = beg + g_deg[2 * NN + node];

    float accST[8], accTS[8], accA[8];
    #pragma unroll
    for (int i = 0; i < 8; i++) { accST[i] = 0.f; accTS[i] = 0.f; accA[i] = 0.f; }

    #pragma unroll 4
    for (int j = beg; j < end; j += 2) {
        int e = j + half;
        if (e < end) {
            int4 mt = g_epack[e];
            int s = mt.x & 0xFFFFF;
            int r = mt.x >> 20;
            if (maskedRole) {
                float cm = __int_as_float(mt.z);
                float f[8];
                ldh8(f, g_hlin16 + (size_t)s * H1DIM + (r ? 64 : 0) + l8 * 8);
                float* acc = r ? accTS : accST;
                #pragma unroll
                for (int i = 0; i < 8; i++) acc[i] += f[i] * cm;
            } else {
                float ca = __int_as_float(mt.y);
                float f[8];
                ldh8(f, g_hlin16 + (size_t)s * H1DIM + 128 + l8 * 8);
                #pragma unroll
                for (int i = 0; i < 8; i++) accA[i] += f[i] * ca;
            }
        }
    }
    #pragma unroll
    for (int i = 0; i < 8; i++) {
        accST[i] += __shfl_xor_sync(0xFFFFFFFFu, accST[i], 16);
        accTS[i] += __shfl_xor_sync(0xFFFFFFFFu, accTS[i], 16);
        accA[i]  += __shfl_xor_sync(0xFFFFFFFFu, accA[i], 16);
    }

    if (lane >= 16) return;
    const __half* hrow = g_hlin16 + (size_t)node * H1DIM;
    __nv_bfloat16* orow = g_h1b + (size_t)node * H1DIM;
    int c = l8 * 8;
    if (maskedRole) {
        float dv = g_dinv[node];
        float self = dv * dv;
        float h[8], o[8];
        ldh8(h, hrow + c);
        #pragma unroll
        for (int i = 0; i < 8; i++) o[i] = fmaxf(accST[i] + h[i] * self + b_st[c + i], 0.f);
        stb8(orow + c, o);
        dv = g_dinv[NN + node];
        self = dv * dv;
        ldh8(h, hrow + 64 + c);
        #pragma unroll
        for (int i = 0; i < 8; i++) o[i] = fmaxf(accTS[i] + h[i] * self + b_ts[c + i], 0.f);
        stb8(orow + 64 + c, o);
    } else {
        float dv = g_dinv[2 * NN + node];
        float self = dv * dv;
        float h[8], o[8];
        ldh8(h, hrow + 128 + c);
        #pragma unroll
        for (int i = 0; i < 8; i++) o[i] = fmaxf(accA[i] + h[i] * self + b1[c + i], 0.f);
        stb8(orow + 128 + c, o);
    }
}

// ---------------- layer-2 CSR gather (fp16 in, fp16 out) ----------------
__global__ void gather2(const float* __restrict__ b2) {
    int node = blockIdx.x * (blockDim.x >> 5) + (threadIdx.x >> 5);
    if (node >= NN) return;
    int lane = threadIdx.x & 31;
    int l = lane & 15;
    int half = lane >> 4;
    int beg = g_off[node];
    int end = beg + g_deg[2 * NN + node];

    float acc[8];
    #pragma unroll
    for (int i = 0; i < 8; i++) acc[i] = 0.f;

    #pragma unroll 4
    for (int j = beg; j < end; j += 2) {
        int e = j + half;
        if (e < end) {
            int4 mt = g_epack[e];
            int s = mt.x & 0xFFFFF;
            float ca = __int_as_float(mt.y);
            float f[8];
            ldh8(f, g_h2lin16 + (size_t)s * H2DIM + l * 8);
            #pragma unroll
            for (int i = 0; i < 8; i++) acc[i] += f[i] * ca;
        }
    }
    #pragma unroll
    for (int i = 0; i < 8; i++) acc[i] += __shfl_xor_sync(0xFFFFFFFFu, acc[i], 16);

    if (lane >= 16) return;
    float dv = g_dinv[2 * NN + node];
    float self = dv * dv;
    int c = l * 8;
    float h[8], o[8];
    ldh8(h, g_h2lin16 + (size_t)node * H2DIM + c);
    #pragma unroll
    for (int i = 0; i < 8; i++) o[i] = acc[i] + h[i] * self + b2[c + i];
    sth8(g_h2_16 + (size_t)node * H2DIM + c, o);
}

// ---------------- layer-3 CSR gather + log_softmax ----------------
__global__ void gather3(float* __restrict__ out, const float* __restrict__ b3) {
    int node = blockIdx.x * (blockDim.x >> 5) + (threadIdx.x >> 5);
    if (node >= NN) return;
    int lane = threadIdx.x & 31;
    int half = lane >> 4;
    int l16 = lane & 15;
    int beg = g_off[node];
    int end = beg + g_deg[2 * NN + node];

    float acc = 0.f;
    #pragma unroll 4
    for (int idx = beg + half; idx < end; idx += 2) {
        int4 mt = g_epack[idx];
        int s = mt.x & 0xFFFFF;
        float ca = __int_as_float(mt.y);
        acc += g_h3lin[(size_t)s * NCLS + l16] * ca;
    }
    acc += __shfl_down_sync(0xFFFFFFFFu, acc, 16);

    float dv = g_dinv[2 * NN + node];
    float self = dv * dv;
    float v = acc + g_h3lin[(size_t)node * NCLS + l16] * self + b3[l16];

    float m = v;
    #pragma unroll
    for (int o = 8; o > 0; o >>= 1) m = fmaxf(m, __shfl_xor_sync(0xFFFFFFFFu, m, o, 16));
    float s = expf(v - m);
    #pragma unroll
    for (int o = 8; o > 0; o >>= 1) s += __shfl_xor_sync(0xFFFFFFFFu, s, o, 16);
    float l = logf(s);
    if (lane < 16) out[(size_t)node * NCLS + l16] = v - m - l;
}

// ---------------- host launcher ----------------
extern "C" void kernel_launch(void* const* d_in, const int* in_sizes, int n_in,
                              void* d_out, int out_size) {
    const float* x    = (const float*)d_in[0];
    const int*   eidx = (const int*)d_in[1];
    const int    E    = in_sizes[1] / 2;
    const int*   src  = eidx;
    const int*   dst  = eidx + E;
    const int*   rev  = (const int*)d_in[2];
    const float* W_st = (const float*)d_in[3];
    const float* b_st = (const float*)d_in[4];
    const float* W_ts = (const float*)d_in[5];
    const float* b_ts = (const float*)d_in[6];
    const float* W1   = (const float*)d_in[7];
    const float* b1   = (const float*)d_in[8];
    const float* W2   = (const float*)d_in[9];
    const float* b2   = (const float*)d_in[10];
    const float* W3   = (const float*)d_in[11];
    const float* b3   = (const float*)d_in[12];
    float* out = (float*)d_out;

    float *h3lin;
    __half *hlin16, *h2lin16, *h2_16;
    __nv_bfloat16 *h1b, *B1hi, *B1lo, *B2hi, *B2lo;
    cudaGetSymbolAddress((void**)&hlin16,  g_hlin16);
    cudaGetSymbolAddress((void**)&h2lin16, g_h2lin16);
    cudaGetSymbolAddress((void**)&h2_16,   g_h2_16);
    cudaGetSymbolAddress((void**)&h3lin,   g_h3lin);
    cudaGetSymbolAddress((void**)&h1b,     g_h1b);
    cudaGetSymbolAddress((void**)&B1hi,    g_B1hi);
    cudaGetSymbolAddress((void**)&B1lo,    g_B1lo);
    cudaGetSymbolAddress((void**)&B2hi,    g_B2hi);
    cudaGetSymbolAddress((void**)&B2lo,    g_B2lo);

    cudaFuncSetAttribute(mma_gemm<2>, cudaFuncAttributeMaxDynamicSharedMemorySize, 110000);
    cudaFuncSetAttribute(mma_gemm<0>, cudaFuncAttributeMaxDynamicSharedMemorySize, 110000);

    const int nb = (NN + 255) / 256;
    const int gblocks = (NN + 127) / 128;   // 782

    // ---- prep (launches 1-3) ----
    wprep1<<<(3 * 64 * F_IN + 255) / 256, 256>>>(W_st, W_ts, W1);
    wprep2<<<(2 * 64 * H1DIM + 255) / 256, 256>>>(W2);
    zero_deg<<<(3 * NN + 255) / 256, 256>>>();

    // ---- layer-1 GEMM (launch #4 -> profiled) ----
    {
        int smem = 384 * (F_IN + 8) * 2;    // 104448
        mma_gemm<2><<<dim3(3, gblocks), 256, smem>>>(x, nullptr, B1hi, B1lo, hlin16, NN, F_IN, 3);
    }

    // ---- CSR build ----
    deg_kernel<<<(E + 255) / 256, 256>>>(dst, rev, E);
    scan_block<<<nb, 256>>>();
    scan_partials<<<1, 512>>>(nb);
    scan_add_dinv<<<(3 * NN + 255) / 256, 256>>>();
    fill_csr<<<(E + 255) / 256, 256>>>(src, dst, rev, E);

    // ---- layer 1 aggregate ----
    gather1<<<(NN * 32 + 255) / 256, 256>>>(b_st, b_ts, b1);

    // ---- layer 2 ----
    {
        int smem = 256 * (H1DIM + 8) * 2;   // 102400
        mma_gemm<0><<<dim3(2, gblocks), 256, smem>>>(h1b, nullptr, B2hi, B2lo, h2lin16, NN, H1DIM, 2);
    }
    gather2<<<(NN * 32 + 255) / 256, 256>>>(b2);

    // ---- layer 3 ----
    dim3 g3(1, gblocks);
    sgemm_h<<<g3, 256>>>(h2_16, W3, h3lin, NN, NCLS, H2DIM, NCLS);
    gather3<<<(NN * 32 + 255) / 256, 256>>>(out, b3);
}